// round 3
// baseline (speedup 1.0000x reference)
#include <cuda_runtime.h>
#include <math.h>

#define NN 50000
#define EE 500000
#define ESLN 550000   // EE + NN (edges with self loops)
#define FIN 128
#define HC 256
#define CH 128
#define NCLASS 10

// ---------------- scratch (static __device__ globals; no allocation) -------
__device__ int   g_src[ESLN];
__device__ int   g_dst[ESLN];
__device__ int   g_cnt[NN];
__device__ int   g_cursor[NN];
__device__ int   g_rowptr0[NN + 1];
__device__ int   g_rowptr1[NN + 1];
__device__ int   g_perm0[EE];
__device__ int   g_perm1[ESLN];
__device__ float g_XLR[(size_t)NN * 512];   // [N, 512]: cols 0..255 = xl, 256..511 = xr
__device__ float g_HA[(size_t)NN * HC];
__device__ float g_HB[(size_t)NN * HC];
__device__ float g_partial[256];
__device__ float g_wmean;

// ---------------- small utility kernels ------------------------------------
__global__ void zero_int_kernel(int* p, int n) {
    int i = blockIdx.x * blockDim.x + threadIdx.x;
    if (i < n) p[i] = 0;
}

// edge_index may be int32 or int64 depending on JAX x64 config.
// For int64 storage every odd 32-bit word (the high half) is 0 since values < 2^31.
__global__ void convert_edges_kernel(const unsigned int* __restrict__ ei,
                                     int* __restrict__ src, int* __restrict__ dst) {
    __shared__ int s_is64;
    if (threadIdx.x == 0) {
        unsigned int acc = 0;
#pragma unroll
        for (int k = 0; k < 32; k++) acc |= ei[2 * k + 1];
        s_is64 = (acc == 0u) ? 1 : 0;
    }
    __syncthreads();
    int is64 = s_is64;
    int i = blockIdx.x * blockDim.x + threadIdx.x;
    if (i >= ESLN) return;
    if (i < EE) {
        int s, d;
        if (is64) {
            const long long* p = reinterpret_cast<const long long*>(ei);
            s = (int)p[i];
            d = (int)p[EE + i];
        } else {
            const int* p = reinterpret_cast<const int*>(ei);
            s = p[i];
            d = p[EE + i];
        }
        src[i] = s;
        dst[i] = d;
    } else {
        int v = i - EE;  // self loop
        src[i] = v;
        dst[i] = v;
    }
}

__global__ void mean_partial_kernel(const float* __restrict__ w) {
    __shared__ float s[256];
    float acc = 0.f;
    for (int i = blockIdx.x * 256 + threadIdx.x; i < EE; i += 256 * 256) acc += w[i];
    s[threadIdx.x] = acc;
    __syncthreads();
    for (int off = 128; off > 0; off >>= 1) {
        if (threadIdx.x < off) s[threadIdx.x] += s[threadIdx.x + off];
        __syncthreads();
    }
    if (threadIdx.x == 0) g_partial[blockIdx.x] = s[0];
}

__global__ void mean_final_kernel() {
    __shared__ float s[256];
    s[threadIdx.x] = g_partial[threadIdx.x];
    __syncthreads();
    for (int off = 128; off > 0; off >>= 1) {
        if (threadIdx.x < off) s[threadIdx.x] += s[threadIdx.x + off];
        __syncthreads();
    }
    if (threadIdx.x == 0) g_wmean = s[0] / (float)EE;
}

__global__ void hist_kernel(const int* __restrict__ dst, int* __restrict__ cnt, int count) {
    int e = blockIdx.x * blockDim.x + threadIdx.x;
    if (e < count) atomicAdd(&cnt[dst[e]], 1);
}

// Single-block exclusive scan over NN counts; writes rowptr[0..NN] and cursor copy.
__global__ void scan_kernel(const int* __restrict__ cnt, int* __restrict__ rowptr,
                            int* __restrict__ cursor) {
    __shared__ int sdata[1024];
    __shared__ int s_carry;
    int t = threadIdx.x;
    if (t == 0) s_carry = 0;
    __syncthreads();
    for (int base = 0; base < NN; base += 1024) {
        int i = base + t;
        int v = (i < NN) ? cnt[i] : 0;
        sdata[t] = v;
        __syncthreads();
        for (int off = 1; off < 1024; off <<= 1) {
            int x = sdata[t];
            int y = (t >= off) ? sdata[t - off] : 0;
            __syncthreads();
            sdata[t] = x + y;
            __syncthreads();
        }
        int incl = sdata[t];
        int carry = s_carry;
        if (i < NN) {
            int ex = carry + incl - v;
            rowptr[i] = ex;
            cursor[i] = ex;
        }
        __syncthreads();
        if (t == 1023) s_carry = carry + incl;
        __syncthreads();
    }
    if (t == 0) rowptr[NN] = s_carry;
}

__global__ void scatter_kernel(const int* __restrict__ dst, int* __restrict__ cursor,
                               int* __restrict__ perm, int count) {
    int e = blockIdx.x * blockDim.x + threadIdx.x;
    if (e < count) {
        int p = atomicAdd(&cursor[dst[e]], 1);
        perm[p] = e;
    }
}

// ---------------- tf32 helpers ----------------------------------------------
// cvt.rna.tf32.f32 needs a .b32 destination register ("=r"), not "=f".
__device__ __forceinline__ float f2tf32(float x) {
    unsigned int r;
    asm("cvt.rna.tf32.f32 %0, %1;" : "=r"(r) : "f"(x));
    return __uint_as_float(r);
}

__device__ __forceinline__ void mma_tf32(float* c, const float4& a, float b0, float b1) {
    asm volatile(
        "mma.sync.aligned.m16n8k8.row.col.f32.tf32.tf32.f32 "
        "{%0,%1,%2,%3}, {%4,%5,%6,%7}, {%8,%9}, {%0,%1,%2,%3};"
        : "+f"(c[0]), "+f"(c[1]), "+f"(c[2]), "+f"(c[3])
        : "r"(__float_as_uint(a.x)), "r"(__float_as_uint(a.y)),
          "r"(__float_as_uint(a.z)), "r"(__float_as_uint(a.w)),
          "r"(__float_as_uint(b0)), "r"(__float_as_uint(b1)));
}

// ---------------- GEMM: C[N,512] = A[N,K] @ [Wl | Wr] + [bl | br] ----------
// 3xTF32 tensor-core GEMM. Block tile 128x128, BK=16, 8 warps (2x4), each warp
// 64x32 (4x4 m16n8 tiles). Smem holds fragment-permuted hi/lo tiles so each
// fragment is a single LDS.128 / LDS.64. Double-buffered (64KB dynamic smem),
// global loads register-prefetched one tile ahead.
__global__ __launch_bounds__(256) void gemm_tf32_kernel(
    const float* __restrict__ A, int Mrows, int K,
    const float* __restrict__ Wl, const float* __restrict__ Wr,
    const float* __restrict__ bl, const float* __restrict__ br,
    float* __restrict__ Cmat) {
    extern __shared__ float sdyn[];  // 2 stages x 8192 floats
    const float* W = (blockIdx.y < 2) ? Wl : Wr;
    const float* bptr = (blockIdx.y < 2) ? bl : br;
    const int colbase = (blockIdx.y & 1) * 128;
    const int brow = blockIdx.x * 128;
    const int tid = threadIdx.x;
    const int lane = tid & 31;
    const int warp = tid >> 5;
    const int wm = warp >> 2;  // 0..1
    const int wn = warp & 3;   // 0..3

    float acc[4][4][4];
#pragma unroll
    for (int i = 0; i < 4; i++)
#pragma unroll
        for (int j = 0; j < 4; j++)
#pragma unroll
            for (int r = 0; r < 4; r++) acc[i][j][r] = 0.f;

    float4 pa[2], pb[2];

    auto loadg = [&](int kt) {
#pragma unroll
        for (int i = 0; i < 2; i++) {
            int f = tid + i * 256;
            int row = f >> 2;
            int grow = brow + row;
            int kc = kt + (f & 3) * 4;
            pa[i] = (grow < Mrows)
                        ? *reinterpret_cast<const float4*>(A + (size_t)grow * K + kc)
                        : make_float4(0.f, 0.f, 0.f, 0.f);
        }
#pragma unroll
        for (int i = 0; i < 2; i++) {
            int f = tid + i * 256;
            int kr = f >> 5;
            int col = colbase + (f & 31) * 4;
            pb[i] = *reinterpret_cast<const float4*>(W + (size_t)(kt + kr) * HC + col);
        }
    };

    auto stg = [&](float* S) {
        // A tile: 128 rows x 16 k, split to tf32 hi/lo, fragment-permuted.
#pragma unroll
        for (int i = 0; i < 2; i++) {
            int f = tid + i * 256;
            int row = f >> 2;
            int r = row & 15, mt = row >> 4;
            int kg = (f & 3) * 4;        // 0,4,8,12
            int ktile = kg >> 3;         // 0 or 1
            int regbase = (r >= 8) ? 1 : 0;
            int tb = (r & 7) * 4;
            const float* v = reinterpret_cast<const float*>(&pa[i]);
#pragma unroll
            for (int e = 0; e < 4; e++) {
                int kk = (kg & 7) + e;   // 0..7
                int reg = regbase + ((kk >= 4) ? 2 : 0);
                int t = tb + (kk & 3);
                int addr = ((mt * 2 + ktile) * 32 + t) * 4 + reg;
                float hi = f2tf32(v[e]);
                S[addr] = hi;
                S[2048 + addr] = f2tf32(v[e] - hi);
            }
        }
        // B tile: 16 k x 128 cols
#pragma unroll
        for (int i = 0; i < 2; i++) {
            int f = tid + i * 256;
            int kr = f >> 5;             // 0..15
            int ktile = kr >> 3, kk = kr & 7;
            int reg = (kk >= 4) ? 1 : 0;
            int cg = (f & 31) * 4;
            const float* v = reinterpret_cast<const float*>(&pb[i]);
#pragma unroll
            for (int e = 0; e < 4; e++) {
                int col = cg + e;
                int nt = col >> 3, nn = col & 7;
                int t = nn * 4 + (kk & 3);
                int addr = 4096 + ((nt * 2 + ktile) * 32 + t) * 2 + reg;
                float hi = f2tf32(v[e]);
                S[addr] = hi;
                S[2048 + addr] = f2tf32(v[e] - hi);
            }
        }
    };

    const int nIters = K >> 4;
    loadg(0);
    stg(sdyn);
    __syncthreads();
    int buf = 0;
    for (int it = 0; it < nIters; it++) {
        if (it + 1 < nIters) loadg((it + 1) << 4);
        const float* S = sdyn + buf * 8192;
#pragma unroll
        for (int ks = 0; ks < 2; ks++) {
            float4 ah[4], alo[4];
            float2 bh[4], blo[4];
#pragma unroll
            for (int t = 0; t < 4; t++) {
                const float* p = S + (((wm * 4 + t) * 2 + ks) * 32 + lane) * 4;
                ah[t] = *reinterpret_cast<const float4*>(p);
                alo[t] = *reinterpret_cast<const float4*>(p + 2048);
            }
#pragma unroll
            for (int t = 0; t < 4; t++) {
                const float* p = S + 4096 + (((wn * 4 + t) * 2 + ks) * 32 + lane) * 2;
                bh[t] = *reinterpret_cast<const float2*>(p);
                blo[t] = *reinterpret_cast<const float2*>(p + 2048);
            }
#pragma unroll
            for (int i = 0; i < 4; i++)
#pragma unroll
                for (int j = 0; j < 4; j++) {
                    mma_tf32(acc[i][j], ah[i], bh[j].x, bh[j].y);
                    mma_tf32(acc[i][j], alo[i], bh[j].x, bh[j].y);
                    mma_tf32(acc[i][j], ah[i], blo[j].x, blo[j].y);
                }
        }
        if (it + 1 < nIters) stg(sdyn + (buf ^ 1) * 8192);
        __syncthreads();
        buf ^= 1;
    }

    // epilogue: bias add + store (c-frag mapping for m16n8)
    int r0 = lane >> 2;
    int c0 = (lane & 3) * 2;
#pragma unroll
    for (int j = 0; j < 4; j++) {
        int localcol = wn * 32 + j * 8 + c0;
        float b0v = bptr[colbase + localcol];
        float b1v = bptr[colbase + localcol + 1];
        int gcol = blockIdx.y * 128 + localcol;
#pragma unroll
        for (int i = 0; i < 4; i++) {
            int grow = brow + wm * 64 + i * 16 + r0;
            if (grow < Mrows) {
                float2 v = make_float2(acc[i][j][0] + b0v, acc[i][j][1] + b1v);
                *reinterpret_cast<float2*>(Cmat + (size_t)grow * 512 + gcol) = v;
            }
            if (grow + 8 < Mrows) {
                float2 v = make_float2(acc[i][j][2] + b0v, acc[i][j][3] + b1v);
                *reinterpret_cast<float2*>(Cmat + (size_t)(grow + 8) * 512 + gcol) = v;
            }
        }
    }
}

// ---------------- fused GATv2 node kernel (online softmax) -----------------
__global__ __launch_bounds__(256) void gat_node_kernel(
    const float* __restrict__ XLR,
    const int* __restrict__ rowptr, const int* __restrict__ perm,
    const int* __restrict__ src, const float* __restrict__ wgt,
    const float* __restrict__ att, const float* __restrict__ We,
    const float* __restrict__ bias, float* __restrict__ Hout) {
    int wid = (blockIdx.x * blockDim.x + threadIdx.x) >> 5;
    if (wid >= NN * 2) return;
    int lane = threadIdx.x & 31;
    int node = wid >> 1;
    int h = wid & 1;
    int base = h * CH + lane * 4;
    const float4 xr = *reinterpret_cast<const float4*>(XLR + (size_t)node * 512 + 256 + base);
    const float4 av = *reinterpret_cast<const float4*>(att + base);
    const float4 wv = *reinterpret_cast<const float4*>(We + base);
    float m = -3.0e38f, d = 0.f;
    float4 acc = make_float4(0.f, 0.f, 0.f, 0.f);
    int i0 = rowptr[node], i1 = rowptr[node + 1];
    float wmean = g_wmean;
    for (int idx = i0; idx < i1; idx++) {
        int e = perm[idx];
        int s = src[e];
        float ea = (e < EE) ? __ldg(wgt + e) : wmean;
        float4 xl = *reinterpret_cast<const float4*>(XLR + (size_t)s * 512 + base);
        float t0 = xl.x + xr.x + ea * wv.x;
        float t1 = xl.y + xr.y + ea * wv.y;
        float t2 = xl.z + xr.z + ea * wv.z;
        float t3 = xl.w + xr.w + ea * wv.w;
        t0 = t0 > 0.f ? t0 : 0.2f * t0;
        t1 = t1 > 0.f ? t1 : 0.2f * t1;
        t2 = t2 > 0.f ? t2 : 0.2f * t2;
        t3 = t3 > 0.f ? t3 : 0.2f * t3;
        float p = t0 * av.x + t1 * av.y + t2 * av.z + t3 * av.w;
#pragma unroll
        for (int off = 16; off >= 1; off >>= 1) p += __shfl_xor_sync(0xffffffffu, p, off);
        float nm = fmaxf(m, p);
        float sc = expf(m - nm);   // 0 on first edge (m = -3e38)
        float pe = expf(p - nm);
        d = d * sc + pe;
        acc.x = acc.x * sc + pe * xl.x;
        acc.y = acc.y * sc + pe * xl.y;
        acc.z = acc.z * sc + pe * xl.z;
        acc.w = acc.w * sc + pe * xl.w;
        m = nm;
    }
    float inv = (i1 > i0) ? 1.f / (d + 1e-16f) : 0.f;
    const float4 bv = *reinterpret_cast<const float4*>(bias + base);
    float o0 = acc.x * inv + bv.x;
    float o1 = acc.y * inv + bv.y;
    float o2 = acc.z * inv + bv.z;
    float o3 = acc.w * inv + bv.w;
    o0 = o0 > 0.f ? o0 : expm1f(o0);
    o1 = o1 > 0.f ? o1 : expm1f(o1);
    o2 = o2 > 0.f ? o2 : expm1f(o2);
    o3 = o3 > 0.f ? o3 : expm1f(o3);
    float4 outv = make_float4(o0, o1, o2, o3);
    *reinterpret_cast<float4*>(Hout + (size_t)node * HC + base) = outv;
}

// ---------------- final classifier ------------------------------------------
__global__ __launch_bounds__(256) void fc_kernel(const float* __restrict__ Hin,
                                                 const float* __restrict__ W,
                                                 const float* __restrict__ b,
                                                 float* __restrict__ out) {
    int wid = (blockIdx.x * blockDim.x + threadIdx.x) >> 5;
    if (wid >= NN) return;
    int lane = threadIdx.x & 31;
    float acc[NCLASS];
#pragma unroll
    for (int k = 0; k < NCLASS; k++) acc[k] = 0.f;
#pragma unroll
    for (int j0 = 0; j0 < HC; j0 += 32) {
        float hv = Hin[(size_t)wid * HC + j0 + lane];
        const float* wr = W + (size_t)(j0 + lane) * NCLASS;
#pragma unroll
        for (int k = 0; k < NCLASS; k++) acc[k] += hv * __ldg(wr + k);
    }
#pragma unroll
    for (int k = 0; k < NCLASS; k++) {
#pragma unroll
        for (int off = 16; off >= 1; off >>= 1)
            acc[k] += __shfl_xor_sync(0xffffffffu, acc[k], off);
    }
    if (lane == 0) {
#pragma unroll
        for (int k = 0; k < NCLASS; k++) out[(size_t)wid * NCLASS + k] = acc[k] + b[k];
    }
}

// ---------------- launch -----------------------------------------------------
extern "C" void kernel_launch(void* const* d_in, const int* in_sizes, int n_in,
                              void* d_out, int out_size) {
    const float* x = (const float*)d_in[0];
    const void* ei = d_in[1];
    const float* wgt = (const float*)d_in[2];
    const float *Wl[3], *bl[3], *Wr[3], *br[3], *We[3], *att[3], *bb[3];
    for (int i = 0; i < 3; i++) {
        int bse = 3 + 7 * i;
        Wl[i] = (const float*)d_in[bse + 0];
        bl[i] = (const float*)d_in[bse + 1];
        Wr[i] = (const float*)d_in[bse + 2];
        br[i] = (const float*)d_in[bse + 3];
        We[i] = (const float*)d_in[bse + 4];
        att[i] = (const float*)d_in[bse + 5];
        bb[i] = (const float*)d_in[bse + 6];
    }
    const float* fcW = (const float*)d_in[24];
    const float* fcb = (const float*)d_in[25];
    float* out = (float*)d_out;

    int *psrc, *pdst, *pcnt, *pcursor, *prow0, *prow1, *pperm0, *pperm1;
    float *pXLR, *pHA, *pHB;
    cudaGetSymbolAddress((void**)&psrc, g_src);
    cudaGetSymbolAddress((void**)&pdst, g_dst);
    cudaGetSymbolAddress((void**)&pcnt, g_cnt);
    cudaGetSymbolAddress((void**)&pcursor, g_cursor);
    cudaGetSymbolAddress((void**)&prow0, g_rowptr0);
    cudaGetSymbolAddress((void**)&prow1, g_rowptr1);
    cudaGetSymbolAddress((void**)&pperm0, g_perm0);
    cudaGetSymbolAddress((void**)&pperm1, g_perm1);
    cudaGetSymbolAddress((void**)&pXLR, g_XLR);
    cudaGetSymbolAddress((void**)&pHA, g_HA);
    cudaGetSymbolAddress((void**)&pHB, g_HB);

    // allow 64KB dynamic smem for the tensor GEMM (host-side attr, not captured)
    cudaFuncSetAttribute(gemm_tf32_kernel,
                         cudaFuncAttributeMaxDynamicSharedMemorySize, 65536);

    // edge decode + self loops
    convert_edges_kernel<<<(ESLN + 255) / 256, 256>>>((const unsigned int*)ei, psrc, pdst);
    // mean of weight (for self-loop edge attr)
    mean_partial_kernel<<<256, 256>>>(wgt);
    mean_final_kernel<<<1, 256>>>();

    // CSR 0 (no self loops, layer 0)
    zero_int_kernel<<<(NN + 255) / 256, 256>>>(pcnt, NN);
    hist_kernel<<<(EE + 255) / 256, 256>>>(pdst, pcnt, EE);
    scan_kernel<<<1, 1024>>>(pcnt, prow0, pcursor);
    scatter_kernel<<<(EE + 255) / 256, 256>>>(pdst, pcursor, pperm0, EE);
    // CSR 1 (with self loops, layers 1-2)
    zero_int_kernel<<<(NN + 255) / 256, 256>>>(pcnt, NN);
    hist_kernel<<<(ESLN + 255) / 256, 256>>>(pdst, pcnt, ESLN);
    scan_kernel<<<1, 1024>>>(pcnt, prow1, pcursor);
    scatter_kernel<<<(ESLN + 255) / 256, 256>>>(pdst, pcursor, pperm1, ESLN);

    dim3 ggrid((NN + 127) / 128, 4);
    int node_blocks = (NN * 2 * 32 + 255) / 256;  // one warp per (node, head)

    // Layer 0
    gemm_tf32_kernel<<<ggrid, 256, 65536>>>(x, NN, FIN, Wl[0], Wr[0], bl[0], br[0], pXLR);
    gat_node_kernel<<<node_blocks, 256>>>(pXLR, prow0, pperm0, psrc, wgt,
                                          att[0], We[0], bb[0], pHA);
    // Layer 1
    gemm_tf32_kernel<<<ggrid, 256, 65536>>>(pHA, NN, HC, Wl[1], Wr[1], bl[1], br[1], pXLR);
    gat_node_kernel<<<node_blocks, 256>>>(pXLR, prow1, pperm1, psrc, wgt,
                                          att[1], We[1], bb[1], pHB);
    // Layer 2
    gemm_tf32_kernel<<<ggrid, 256, 65536>>>(pHB, NN, HC, Wl[2], Wr[2], bl[2], br[2], pXLR);
    gat_node_kernel<<<node_blocks, 256>>>(pXLR, prow1, pperm1, psrc, wgt,
                                          att[2], We[2], bb[2], pHA);
    // Classifier
    fc_kernel<<<(NN * 32 + 255) / 256, 256>>>(pHA, fcW, fcb, out);
}

// round 4
// speedup vs baseline: 2.3000x; 2.3000x over previous
#include <cuda_runtime.h>
#include <cuda_bf16.h>
#include <math.h>
#include <stdint.h>

#define NN 50000
#define EE 500000
#define ESLN 550000   // EE + NN (edges with self loops)
#define FIN 128
#define HC 256
#define CH 128
#define NCLASS 10

// ---------------- scratch (static __device__ globals; no allocation) -------
__device__ int   g_src[ESLN];
__device__ int   g_dst[ESLN];
__device__ int   g_cnt[NN];
__device__ int   g_cursor[NN];
__device__ int   g_rowptr0[NN + 1];
__device__ int   g_rowptr1[NN + 1];
__device__ int   g_perm0[EE];
__device__ int   g_perm1[ESLN];
__device__ float g_XLR[(size_t)NN * 512];   // [N, 512]: cols 0..255 = xl, 256..511 = xr
__device__ float g_HA[(size_t)NN * HC];
__device__ float g_HB[(size_t)NN * HC];
__device__ float g_partial[256];
__device__ float g_wmean;

// ---------------- small utility kernels ------------------------------------
__global__ void zero_int_kernel(int* p, int n) {
    int i = blockIdx.x * blockDim.x + threadIdx.x;
    if (i < n) p[i] = 0;
}

// edge_index may be int32 or int64 depending on JAX x64 config.
// For int64 storage every odd 32-bit word (the high half) is 0 since values < 2^31.
__global__ void convert_edges_kernel(const unsigned int* __restrict__ ei,
                                     int* __restrict__ src, int* __restrict__ dst) {
    __shared__ int s_is64;
    if (threadIdx.x == 0) {
        unsigned int acc = 0;
#pragma unroll
        for (int k = 0; k < 32; k++) acc |= ei[2 * k + 1];
        s_is64 = (acc == 0u) ? 1 : 0;
    }
    __syncthreads();
    int is64 = s_is64;
    int i = blockIdx.x * blockDim.x + threadIdx.x;
    if (i >= ESLN) return;
    if (i < EE) {
        int s, d;
        if (is64) {
            const long long* p = reinterpret_cast<const long long*>(ei);
            s = (int)p[i];
            d = (int)p[EE + i];
        } else {
            const int* p = reinterpret_cast<const int*>(ei);
            s = p[i];
            d = p[EE + i];
        }
        src[i] = s;
        dst[i] = d;
    } else {
        int v = i - EE;  // self loop
        src[i] = v;
        dst[i] = v;
    }
}

__global__ void mean_partial_kernel(const float* __restrict__ w) {
    __shared__ float s[256];
    float acc = 0.f;
    for (int i = blockIdx.x * 256 + threadIdx.x; i < EE; i += 256 * 256) acc += w[i];
    s[threadIdx.x] = acc;
    __syncthreads();
    for (int off = 128; off > 0; off >>= 1) {
        if (threadIdx.x < off) s[threadIdx.x] += s[threadIdx.x + off];
        __syncthreads();
    }
    if (threadIdx.x == 0) g_partial[blockIdx.x] = s[0];
}

__global__ void mean_final_kernel() {
    __shared__ float s[256];
    s[threadIdx.x] = g_partial[threadIdx.x];
    __syncthreads();
    for (int off = 128; off > 0; off >>= 1) {
        if (threadIdx.x < off) s[threadIdx.x] += s[threadIdx.x + off];
        __syncthreads();
    }
    if (threadIdx.x == 0) g_wmean = s[0] / (float)EE;
}

__global__ void hist_kernel(const int* __restrict__ dst, int* __restrict__ cnt, int count) {
    int e = blockIdx.x * blockDim.x + threadIdx.x;
    if (e < count) atomicAdd(&cnt[dst[e]], 1);
}

// Single-block exclusive scan over NN counts; writes rowptr[0..NN] and cursor copy.
__global__ void scan_kernel(const int* __restrict__ cnt, int* __restrict__ rowptr,
                            int* __restrict__ cursor) {
    __shared__ int sdata[1024];
    __shared__ int s_carry;
    int t = threadIdx.x;
    if (t == 0) s_carry = 0;
    __syncthreads();
    for (int base = 0; base < NN; base += 1024) {
        int i = base + t;
        int v = (i < NN) ? cnt[i] : 0;
        sdata[t] = v;
        __syncthreads();
        for (int off = 1; off < 1024; off <<= 1) {
            int x = sdata[t];
            int y = (t >= off) ? sdata[t - off] : 0;
            __syncthreads();
            sdata[t] = x + y;
            __syncthreads();
        }
        int incl = sdata[t];
        int carry = s_carry;
        if (i < NN) {
            int ex = carry + incl - v;
            rowptr[i] = ex;
            cursor[i] = ex;
        }
        __syncthreads();
        if (t == 1023) s_carry = carry + incl;
        __syncthreads();
    }
    if (t == 0) rowptr[NN] = s_carry;
}

__global__ void scatter_kernel(const int* __restrict__ dst, int* __restrict__ cursor,
                               int* __restrict__ perm, int count) {
    int e = blockIdx.x * blockDim.x + threadIdx.x;
    if (e < count) {
        int p = atomicAdd(&cursor[dst[e]], 1);
        perm[p] = e;
    }
}

// ---------------- bf16 helpers ----------------------------------------------
__device__ __forceinline__ uint32_t pack_bf16(__nv_bfloat16 a, __nv_bfloat16 b) {
    __nv_bfloat162 t = __halves2bfloat162(a, b);  // .x = a (low 16 bits)
    return *reinterpret_cast<uint32_t*>(&t);
}

__device__ __forceinline__ void mma_bf16(float* c, const uint32_t* a, uint32_t b0, uint32_t b1) {
    asm volatile(
        "mma.sync.aligned.m16n8k16.row.col.f32.bf16.bf16.f32 "
        "{%0,%1,%2,%3}, {%4,%5,%6,%7}, {%8,%9}, {%0,%1,%2,%3};"
        : "+f"(c[0]), "+f"(c[1]), "+f"(c[2]), "+f"(c[3])
        : "r"(a[0]), "r"(a[1]), "r"(a[2]), "r"(a[3]), "r"(b0), "r"(b1));
}

// ---------------- GEMM: C[N,512] = A[N,K] @ [Wl | Wr] + [bl | br] ----------
// 3xBF16 tensor-core GEMM (hi/lo split, lo*lo dropped: ~2^-18 rel).
// Block tile 128x128, BK=16 (= one m16n8k16 k-step), 8 warps (2x4), warp tile
// 64x32 (4x4 mma tiles). Smem stages hold fragment-permuted hi/lo tiles:
//   A: [8 mtiles][32 slots x 16B]  slot self-swizzled  (LDS.128 frag loads)
//   B: [16 ntiles][32 slots x 8B]  nt-swizzled         (LDS.64 frag loads)
// All STS <=2-way conflicted, all frag LDS conflict-free (hand-verified).
__global__ __launch_bounds__(256) void gemm_bf16x3_kernel(
    const float* __restrict__ A, int Mrows, int K,
    const float* __restrict__ Wl, const float* __restrict__ Wr,
    const float* __restrict__ bl, const float* __restrict__ br,
    float* __restrict__ Cmat) {
    extern __shared__ uint32_t S[];  // 2 stages x 4096 words (32KB total)
    const float* W = (blockIdx.y < 2) ? Wl : Wr;
    const float* bptr = (blockIdx.y < 2) ? bl : br;
    const int colbase = (blockIdx.y & 1) * 128;
    const int brow = blockIdx.x * 128;
    const int tid = threadIdx.x;
    const int lane = tid & 31;
    const int warp = tid >> 5;
    const int wm = warp >> 2;  // 0..1
    const int wn = warp & 3;   // 0..3

    float acc[4][4][4];
#pragma unroll
    for (int i = 0; i < 4; i++)
#pragma unroll
        for (int j = 0; j < 4; j++)
#pragma unroll
            for (int r = 0; r < 4; r++) acc[i][j][r] = 0.f;

    // per-thread tile cells:
    //  A: two cells f = tid + i*256: row = f>>2 (0..127), kg = (f&3)*4
    //  B: one cell: n4 = (lane)*4 with warp giving kp: kp = tid>>5 (0..7), n4 = (tid&31)*4
    float4 pa[2], pb[2];

    auto loadg = [&](int kt) {
#pragma unroll
        for (int i = 0; i < 2; i++) {
            int f = tid + i * 256;
            int grow = brow + (f >> 2);
            int kc = kt + (f & 3) * 4;
            pa[i] = (grow < Mrows)
                        ? *reinterpret_cast<const float4*>(A + (size_t)grow * K + kc)
                        : make_float4(0.f, 0.f, 0.f, 0.f);
        }
        int kp = tid >> 5;
        int n4 = (tid & 31) * 4;
        const float* w0 = W + (size_t)(kt + 2 * kp) * HC + colbase + n4;
        pb[0] = *reinterpret_cast<const float4*>(w0);
        pb[1] = *reinterpret_cast<const float4*>(w0 + HC);
    };

    auto stg = [&](uint32_t* St) {
        // ---- A tile ----
#pragma unroll
        for (int i = 0; i < 2; i++) {
            int f = tid + i * 256;
            int row = f >> 2;
            int kg = (f & 3) * 4;
            int mt = row >> 4;
            int rlow = row & 7;
            int regbase = ((row >> 3) & 1) + ((kg >= 8) ? 2 : 0);
            const float* v = reinterpret_cast<const float*>(&pa[i]);
#pragma unroll
            for (int p = 0; p < 2; p++) {
                float x0 = v[2 * p], x1 = v[2 * p + 1];
                __nv_bfloat16 h0 = __float2bfloat16_rn(x0);
                __nv_bfloat16 h1 = __float2bfloat16_rn(x1);
                __nv_bfloat16 l0 = __float2bfloat16_rn(x0 - __bfloat162float(h0));
                __nv_bfloat16 l1 = __float2bfloat16_rn(x1 - __bfloat162float(h1));
                int slot = rlow * 4 + ((kg >> 1) & 3) + p;
                int phys = slot ^ ((slot >> 3) & 3);
                int widx = (mt * 32 + phys) * 4 + regbase;
                St[widx] = pack_bf16(h0, h1);
                St[1024 + widx] = pack_bf16(l0, l1);
            }
        }
        // ---- B tile ----
        {
            int kp = tid >> 5;
            int n4 = (tid & 31) * 4;
            int reg = kp >> 2;
            int kc = kp & 3;
            const float* v0 = reinterpret_cast<const float*>(&pb[0]);
            const float* v1 = reinterpret_cast<const float*>(&pb[1]);
#pragma unroll
            for (int e = 0; e < 4; e++) {
                float x0 = v0[e], x1 = v1[e];
                __nv_bfloat16 h0 = __float2bfloat16_rn(x0);
                __nv_bfloat16 h1 = __float2bfloat16_rn(x1);
                __nv_bfloat16 l0 = __float2bfloat16_rn(x0 - __bfloat162float(h0));
                __nv_bfloat16 l1 = __float2bfloat16_rn(x1 - __bfloat162float(h1));
                int n = n4 + e;
                int nt = n >> 3;
                int slot = (n & 7) * 4 + kc;
                int phys = slot ^ (nt & 15);
                int widx = 2048 + (nt * 32 + phys) * 2 + reg;
                St[widx] = pack_bf16(h0, h1);
                St[1024 + widx] = pack_bf16(l0, l1);
            }
        }
    };

    const int nIters = K >> 4;
    loadg(0);
    stg(S);
    __syncthreads();
    int buf = 0;
    for (int it = 0; it < nIters; it++) {
        if (it + 1 < nIters) loadg((it + 1) << 4);
        const uint32_t* St = S + buf * 4096;

        uint32_t ah[4][4], alo[4][4], bh[4][2], blo[4][2];
        int aphys = lane ^ ((lane >> 3) & 3);
#pragma unroll
        for (int t = 0; t < 4; t++) {
            const uint32_t* p = St + ((wm * 4 + t) * 32 + aphys) * 4;
            *reinterpret_cast<uint4*>(ah[t]) = *reinterpret_cast<const uint4*>(p);
            *reinterpret_cast<uint4*>(alo[t]) = *reinterpret_cast<const uint4*>(p + 1024);
        }
#pragma unroll
        for (int t = 0; t < 4; t++) {
            int nt = wn * 4 + t;
            int bphys = lane ^ (nt & 15);
            const uint32_t* p = St + 2048 + (nt * 32 + bphys) * 2;
            *reinterpret_cast<uint2*>(bh[t]) = *reinterpret_cast<const uint2*>(p);
            *reinterpret_cast<uint2*>(blo[t]) = *reinterpret_cast<const uint2*>(p + 1024);
        }
#pragma unroll
        for (int i = 0; i < 4; i++)
#pragma unroll
            for (int j = 0; j < 4; j++) {
                mma_bf16(acc[i][j], ah[i], bh[j][0], bh[j][1]);
                mma_bf16(acc[i][j], ah[i], blo[j][0], blo[j][1]);
                mma_bf16(acc[i][j], alo[i], bh[j][0], bh[j][1]);
            }

        if (it + 1 < nIters) stg(S + (buf ^ 1) * 4096);
        __syncthreads();
        buf ^= 1;
    }

    // epilogue: bias add + store (c-frag mapping for m16n8)
    int r0 = lane >> 2;
    int c0 = (lane & 3) * 2;
#pragma unroll
    for (int j = 0; j < 4; j++) {
        int localcol = wn * 32 + j * 8 + c0;
        float b0v = bptr[colbase + localcol];
        float b1v = bptr[colbase + localcol + 1];
        int gcol = blockIdx.y * 128 + localcol;
#pragma unroll
        for (int i = 0; i < 4; i++) {
            int grow = brow + wm * 64 + i * 16 + r0;
            if (grow < Mrows) {
                float2 v = make_float2(acc[i][j][0] + b0v, acc[i][j][1] + b1v);
                *reinterpret_cast<float2*>(Cmat + (size_t)grow * 512 + gcol) = v;
            }
            if (grow + 8 < Mrows) {
                float2 v = make_float2(acc[i][j][2] + b0v, acc[i][j][3] + b1v);
                *reinterpret_cast<float2*>(Cmat + (size_t)(grow + 8) * 512 + gcol) = v;
            }
        }
    }
}

// ---------------- fused GATv2 node kernel (online softmax) -----------------
__global__ __launch_bounds__(256) void gat_node_kernel(
    const float* __restrict__ XLR,
    const int* __restrict__ rowptr, const int* __restrict__ perm,
    const int* __restrict__ src, const float* __restrict__ wgt,
    const float* __restrict__ att, const float* __restrict__ We,
    const float* __restrict__ bias, float* __restrict__ Hout) {
    int wid = (blockIdx.x * blockDim.x + threadIdx.x) >> 5;
    if (wid >= NN * 2) return;
    int lane = threadIdx.x & 31;
    int node = wid >> 1;
    int h = wid & 1;
    int base = h * CH + lane * 4;
    const float4 xr = *reinterpret_cast<const float4*>(XLR + (size_t)node * 512 + 256 + base);
    const float4 av = *reinterpret_cast<const float4*>(att + base);
    const float4 wv = *reinterpret_cast<const float4*>(We + base);
    float m = -3.0e38f, d = 0.f;
    float4 acc = make_float4(0.f, 0.f, 0.f, 0.f);
    int i0 = rowptr[node], i1 = rowptr[node + 1];
    float wmean = g_wmean;
    for (int idx = i0; idx < i1; idx++) {
        int e = perm[idx];
        int s = src[e];
        float ea = (e < EE) ? __ldg(wgt + e) : wmean;
        float4 xl = *reinterpret_cast<const float4*>(XLR + (size_t)s * 512 + base);
        float t0 = xl.x + xr.x + ea * wv.x;
        float t1 = xl.y + xr.y + ea * wv.y;
        float t2 = xl.z + xr.z + ea * wv.z;
        float t3 = xl.w + xr.w + ea * wv.w;
        t0 = t0 > 0.f ? t0 : 0.2f * t0;
        t1 = t1 > 0.f ? t1 : 0.2f * t1;
        t2 = t2 > 0.f ? t2 : 0.2f * t2;
        t3 = t3 > 0.f ? t3 : 0.2f * t3;
        float p = t0 * av.x + t1 * av.y + t2 * av.z + t3 * av.w;
#pragma unroll
        for (int off = 16; off >= 1; off >>= 1) p += __shfl_xor_sync(0xffffffffu, p, off);
        float nm = fmaxf(m, p);
        float sc = expf(m - nm);   // 0 on first edge (m = -3e38)
        float pe = expf(p - nm);
        d = d * sc + pe;
        acc.x = acc.x * sc + pe * xl.x;
        acc.y = acc.y * sc + pe * xl.y;
        acc.z = acc.z * sc + pe * xl.z;
        acc.w = acc.w * sc + pe * xl.w;
        m = nm;
    }
    float inv = (i1 > i0) ? 1.f / (d + 1e-16f) : 0.f;
    const float4 bv = *reinterpret_cast<const float4*>(bias + base);
    float o0 = acc.x * inv + bv.x;
    float o1 = acc.y * inv + bv.y;
    float o2 = acc.z * inv + bv.z;
    float o3 = acc.w * inv + bv.w;
    o0 = o0 > 0.f ? o0 : expm1f(o0);
    o1 = o1 > 0.f ? o1 : expm1f(o1);
    o2 = o2 > 0.f ? o2 : expm1f(o2);
    o3 = o3 > 0.f ? o3 : expm1f(o3);
    float4 outv = make_float4(o0, o1, o2, o3);
    *reinterpret_cast<float4*>(Hout + (size_t)node * HC + base) = outv;
}

// ---------------- final classifier ------------------------------------------
__global__ __launch_bounds__(256) void fc_kernel(const float* __restrict__ Hin,
                                                 const float* __restrict__ W,
                                                 const float* __restrict__ b,
                                                 float* __restrict__ out) {
    int wid = (blockIdx.x * blockDim.x + threadIdx.x) >> 5;
    if (wid >= NN) return;
    int lane = threadIdx.x & 31;
    float acc[NCLASS];
#pragma unroll
    for (int k = 0; k < NCLASS; k++) acc[k] = 0.f;
#pragma unroll
    for (int j0 = 0; j0 < HC; j0 += 32) {
        float hv = Hin[(size_t)wid * HC + j0 + lane];
        const float* wr = W + (size_t)(j0 + lane) * NCLASS;
#pragma unroll
        for (int k = 0; k < NCLASS; k++) acc[k] += hv * __ldg(wr + k);
    }
#pragma unroll
    for (int k = 0; k < NCLASS; k++) {
#pragma unroll
        for (int off = 16; off >= 1; off >>= 1)
            acc[k] += __shfl_xor_sync(0xffffffffu, acc[k], off);
    }
    if (lane == 0) {
#pragma unroll
        for (int k = 0; k < NCLASS; k++) out[(size_t)wid * NCLASS + k] = acc[k] + b[k];
    }
}

// ---------------- launch -----------------------------------------------------
extern "C" void kernel_launch(void* const* d_in, const int* in_sizes, int n_in,
                              void* d_out, int out_size) {
    const float* x = (const float*)d_in[0];
    const void* ei = d_in[1];
    const float* wgt = (const float*)d_in[2];
    const float *Wl[3], *bl[3], *Wr[3], *br[3], *We[3], *att[3], *bb[3];
    for (int i = 0; i < 3; i++) {
        int bse = 3 + 7 * i;
        Wl[i] = (const float*)d_in[bse + 0];
        bl[i] = (const float*)d_in[bse + 1];
        Wr[i] = (const float*)d_in[bse + 2];
        br[i] = (const float*)d_in[bse + 3];
        We[i] = (const float*)d_in[bse + 4];
        att[i] = (const float*)d_in[bse + 5];
        bb[i] = (const float*)d_in[bse + 6];
    }
    const float* fcW = (const float*)d_in[24];
    const float* fcb = (const float*)d_in[25];
    float* out = (float*)d_out;

    int *psrc, *pdst, *pcnt, *pcursor, *prow0, *prow1, *pperm0, *pperm1;
    float *pXLR, *pHA, *pHB;
    cudaGetSymbolAddress((void**)&psrc, g_src);
    cudaGetSymbolAddress((void**)&pdst, g_dst);
    cudaGetSymbolAddress((void**)&pcnt, g_cnt);
    cudaGetSymbolAddress((void**)&pcursor, g_cursor);
    cudaGetSymbolAddress((void**)&prow0, g_rowptr0);
    cudaGetSymbolAddress((void**)&prow1, g_rowptr1);
    cudaGetSymbolAddress((void**)&pperm0, g_perm0);
    cudaGetSymbolAddress((void**)&pperm1, g_perm1);
    cudaGetSymbolAddress((void**)&pXLR, g_XLR);
    cudaGetSymbolAddress((void**)&pHA, g_HA);
    cudaGetSymbolAddress((void**)&pHB, g_HB);

    // edge decode + self loops
    convert_edges_kernel<<<(ESLN + 255) / 256, 256>>>((const unsigned int*)ei, psrc, pdst);
    // mean of weight (for self-loop edge attr)
    mean_partial_kernel<<<256, 256>>>(wgt);
    mean_final_kernel<<<1, 256>>>();

    // CSR 0 (no self loops, layer 0)
    zero_int_kernel<<<(NN + 255) / 256, 256>>>(pcnt, NN);
    hist_kernel<<<(EE + 255) / 256, 256>>>(pdst, pcnt, EE);
    scan_kernel<<<1, 1024>>>(pcnt, prow0, pcursor);
    scatter_kernel<<<(EE + 255) / 256, 256>>>(pdst, pcursor, pperm0, EE);
    // CSR 1 (with self loops, layers 1-2)
    zero_int_kernel<<<(NN + 255) / 256, 256>>>(pcnt, NN);
    hist_kernel<<<(ESLN + 255) / 256, 256>>>(pdst, pcnt, ESLN);
    scan_kernel<<<1, 1024>>>(pcnt, prow1, pcursor);
    scatter_kernel<<<(ESLN + 255) / 256, 256>>>(pdst, pcursor, pperm1, ESLN);

    dim3 ggrid((NN + 127) / 128, 4);
    int node_blocks = (NN * 2 * 32 + 255) / 256;  // one warp per (node, head)
    const int smem = 2 * 4096 * 4;  // 32KB

    // Layer 0
    gemm_bf16x3_kernel<<<ggrid, 256, smem>>>(x, NN, FIN, Wl[0], Wr[0], bl[0], br[0], pXLR);
    gat_node_kernel<<<node_blocks, 256>>>(pXLR, prow0, pperm0, psrc, wgt,
                                          att[0], We[0], bb[0], pHA);
    // Layer 1
    gemm_bf16x3_kernel<<<ggrid, 256, smem>>>(pHA, NN, HC, Wl[1], Wr[1], bl[1], br[1], pXLR);
    gat_node_kernel<<<node_blocks, 256>>>(pXLR, prow1, pperm1, psrc, wgt,
                                          att[1], We[1], bb[1], pHB);
    // Layer 2
    gemm_bf16x3_kernel<<<ggrid, 256, smem>>>(pHB, NN, HC, Wl[2], Wr[2], bl[2], br[2], pXLR);
    gat_node_kernel<<<node_blocks, 256>>>(pXLR, prow1, pperm1, psrc, wgt,
                                          att[2], We[2], bb[2], pHA);
    // Classifier
    fc_kernel<<<(NN * 32 + 255) / 256, 256>>>(pHA, fcW, fcb, out);
}

// round 5
// speedup vs baseline: 2.8716x; 1.2485x over previous
#include <cuda_runtime.h>
#include <cuda_bf16.h>
#include <math.h>
#include <stdint.h>

#define NN 50000
#define EE 500000
#define ESLN 550000   // EE + NN (edges with self loops)
#define FIN 128
#define HC 256
#define CH 128
#define NCLASS 10
#define NB0 49        // ceil(NN/1024)

// ---------------- scratch (static __device__ globals; no allocation) -------
__device__ int   g_src[ESLN];
__device__ int   g_dst[ESLN];
__device__ int   g_cnt[NN];
__device__ int   g_cursor[NN];
__device__ int   g_rowptr0[NN + 1];
__device__ int   g_rowptr1[NN + 1];
__device__ int   g_perm0[EE];
__device__ int   g_perm1[ESLN];
__device__ float g_XLR[(size_t)NN * 512];   // [N,512]: 0..255 = xl, 256..511 = xr
__device__ float g_HA[(size_t)NN * HC];     // final layer f32 output
__device__ __nv_bfloat16 g_Ahi[(size_t)NN * HC];
__device__ __nv_bfloat16 g_Alo[(size_t)NN * HC];
__device__ __nv_bfloat16 g_Whi[640 * 512];  // layer0 rows 0-127, l1 128-383, l2 384-639
__device__ __nv_bfloat16 g_Wlo[640 * 512];
__device__ float g_partial[256];
__device__ float g_wmean;
__device__ int   g_bsum[64];

// ---------------- small utility kernels ------------------------------------
__global__ void zero_int_kernel(int* p, int n) {
    int i = blockIdx.x * blockDim.x + threadIdx.x;
    if (i < n) p[i] = 0;
}

// edge_index may be int32 or int64 depending on JAX x64 config.
__global__ void convert_edges_kernel(const unsigned int* __restrict__ ei,
                                     int* __restrict__ src, int* __restrict__ dst) {
    __shared__ int s_is64;
    if (threadIdx.x == 0) {
        unsigned int acc = 0;
#pragma unroll
        for (int k = 0; k < 32; k++) acc |= ei[2 * k + 1];
        s_is64 = (acc == 0u) ? 1 : 0;
    }
    __syncthreads();
    int is64 = s_is64;
    int i = blockIdx.x * blockDim.x + threadIdx.x;
    if (i >= ESLN) return;
    if (i < EE) {
        int s, d;
        if (is64) {
            const long long* p = reinterpret_cast<const long long*>(ei);
            s = (int)p[i];
            d = (int)p[EE + i];
        } else {
            const int* p = reinterpret_cast<const int*>(ei);
            s = p[i];
            d = p[EE + i];
        }
        src[i] = s;
        dst[i] = d;
    } else {
        int v = i - EE;
        src[i] = v;
        dst[i] = v;
    }
}

__global__ void mean_partial_kernel(const float* __restrict__ w) {
    __shared__ float s[256];
    float acc = 0.f;
    for (int i = blockIdx.x * 256 + threadIdx.x; i < EE; i += 256 * 256) acc += w[i];
    s[threadIdx.x] = acc;
    __syncthreads();
    for (int off = 128; off > 0; off >>= 1) {
        if (threadIdx.x < off) s[threadIdx.x] += s[threadIdx.x + off];
        __syncthreads();
    }
    if (threadIdx.x == 0) g_partial[blockIdx.x] = s[0];
}

__global__ void mean_final_kernel() {
    __shared__ float s[256];
    s[threadIdx.x] = g_partial[threadIdx.x];
    __syncthreads();
    for (int off = 128; off > 0; off >>= 1) {
        if (threadIdx.x < off) s[threadIdx.x] += s[threadIdx.x + off];
        __syncthreads();
    }
    if (threadIdx.x == 0) g_wmean = s[0] / (float)EE;
}

__global__ void hist_kernel(const int* __restrict__ dst, int* __restrict__ cnt, int count) {
    int e = blockIdx.x * blockDim.x + threadIdx.x;
    if (e < count) atomicAdd(&cnt[dst[e]], 1);
}

// ---- 3-phase scan: local scans, block-sum scan, add offsets ----
__global__ void scan_local_kernel(const int* __restrict__ cnt, int* __restrict__ rowptr) {
    __shared__ int s[1024];
    int t = threadIdx.x;
    int i = blockIdx.x * 1024 + t;
    int v = (i < NN) ? cnt[i] : 0;
    s[t] = v;
    __syncthreads();
    for (int off = 1; off < 1024; off <<= 1) {
        int x = s[t];
        int y = (t >= off) ? s[t - off] : 0;
        __syncthreads();
        s[t] = x + y;
        __syncthreads();
    }
    if (i < NN) rowptr[i] = s[t] - v;
    if (t == 1023) g_bsum[blockIdx.x] = s[1023];
}

__global__ void scan_bsum_kernel(int* __restrict__ rowptr) {
    __shared__ int s[64];
    int t = threadIdx.x;
    int v = (t < NB0) ? g_bsum[t] : 0;
    s[t] = v;
    __syncthreads();
    for (int off = 1; off < 64; off <<= 1) {
        int x = s[t];
        int y = (t >= off) ? s[t - off] : 0;
        __syncthreads();
        s[t] = x + y;
        __syncthreads();
    }
    if (t < NB0) g_bsum[t] = s[t] - v;
    if (t == 63) rowptr[NN] = s[63];
}

__global__ void scan_add_kernel(int* __restrict__ rowptr, int* __restrict__ cursor) {
    int i = blockIdx.x * 1024 + threadIdx.x;
    if (i < NN) {
        int r = rowptr[i] + g_bsum[blockIdx.x];
        rowptr[i] = r;
        cursor[i] = r;
    }
}

__global__ void scatter_kernel(const int* __restrict__ dst, int* __restrict__ cursor,
                               int* __restrict__ perm, int count) {
    int e = blockIdx.x * blockDim.x + threadIdx.x;
    if (e < count) {
        int p = atomicAdd(&cursor[dst[e]], 1);
        perm[p] = e;
    }
}

// ---------------- bf16 helpers ----------------------------------------------
__device__ __forceinline__ uint32_t pack_bf16(__nv_bfloat16 a, __nv_bfloat16 b) {
    __nv_bfloat162 t = __halves2bfloat162(a, b);
    return *reinterpret_cast<uint32_t*>(&t);
}

__device__ __forceinline__ void split_bf16(float x, __nv_bfloat16& h, __nv_bfloat16& l) {
    h = __float2bfloat16_rn(x);
    l = __float2bfloat16_rn(x - __bfloat162float(h));
}

__device__ __forceinline__ void mma_bf16(float* c, const uint32_t* a, uint32_t b0, uint32_t b1) {
    asm volatile(
        "mma.sync.aligned.m16n8k16.row.col.f32.bf16.bf16.f32 "
        "{%0,%1,%2,%3}, {%4,%5,%6,%7}, {%8,%9}, {%0,%1,%2,%3};"
        : "+f"(c[0]), "+f"(c[1]), "+f"(c[2]), "+f"(c[3])
        : "r"(a[0]), "r"(a[1]), "r"(a[2]), "r"(a[3]), "r"(b0), "r"(b1));
}

__device__ __forceinline__ void ldsm_x4(uint32_t* r, uint32_t saddr) {
    asm volatile("ldmatrix.sync.aligned.m8n8.x4.shared.b16 {%0,%1,%2,%3}, [%4];"
                 : "=r"(r[0]), "=r"(r[1]), "=r"(r[2]), "=r"(r[3]) : "r"(saddr));
}

__device__ __forceinline__ void ldsm_x4_t(uint32_t* r, uint32_t saddr) {
    asm volatile("ldmatrix.sync.aligned.m8n8.x4.trans.shared.b16 {%0,%1,%2,%3}, [%4];"
                 : "=r"(r[0]), "=r"(r[1]), "=r"(r[2]), "=r"(r[3]) : "r"(saddr));
}

__device__ __forceinline__ void cp_async16(uint32_t saddr, const void* g, int sz) {
    asm volatile("cp.async.cg.shared.global [%0], [%1], 16, %2;"
                 :: "r"(saddr), "l"(g), "r"(sz));
}

// ---------------- conversion kernels ----------------------------------------
__global__ void a_convert_kernel(const float* __restrict__ A,
                                 __nv_bfloat16* __restrict__ hi,
                                 __nv_bfloat16* __restrict__ lo, int total) {
    int i = (blockIdx.x * blockDim.x + threadIdx.x) * 4;
    if (i >= total) return;
    float4 v = *reinterpret_cast<const float4*>(A + i);
    __nv_bfloat16 h0, h1, h2, h3, l0, l1, l2, l3;
    split_bf16(v.x, h0, l0); split_bf16(v.y, h1, l1);
    split_bf16(v.z, h2, l2); split_bf16(v.w, h3, l3);
    uint2 uh = make_uint2(pack_bf16(h0, h1), pack_bf16(h2, h3));
    uint2 ul = make_uint2(pack_bf16(l0, l1), pack_bf16(l2, l3));
    *reinterpret_cast<uint2*>(hi + i) = uh;
    *reinterpret_cast<uint2*>(lo + i) = ul;
}

__global__ void w_convert_kernel(const float* __restrict__ Wl0, const float* __restrict__ Wr0,
                                 const float* __restrict__ Wl1, const float* __restrict__ Wr1,
                                 const float* __restrict__ Wl2, const float* __restrict__ Wr2) {
    int i = blockIdx.x * blockDim.x + threadIdx.x;
    if (i >= 640 * 512) return;
    int row = i >> 9, col = i & 511;
    const float *Wl, *Wr;
    int k;
    if (row < 128) { Wl = Wl0; Wr = Wr0; k = row; }
    else if (row < 384) { Wl = Wl1; Wr = Wr1; k = row - 128; }
    else { Wl = Wl2; Wr = Wr2; k = row - 384; }
    float v = (col < 256) ? Wl[k * 256 + col] : Wr[k * 256 + col - 256];
    __nv_bfloat16 h, l;
    split_bf16(v, h, l);
    g_Whi[i] = h;
    g_Wlo[i] = l;
}

// ---------------- GEMM: C[N,512] = A[N,K] @ W + bias -----------------------
// 3xBF16 with pre-split hi/lo operands. cp.async -> swizzled smem -> ldmatrix
// -> mma. Block 128x128, BK=32, 8 warps (2x4), warp tile 64x32.
// Smem per stage (16B chunks): Ahi[512] Alo[512] Bhi[512] Blo[512] = 32KB; x2.
__global__ __launch_bounds__(256) void gemm_bf16_ldsm_kernel(
    const __nv_bfloat16* __restrict__ Ahi, const __nv_bfloat16* __restrict__ Alo,
    int Mrows, int K,
    const __nv_bfloat16* __restrict__ Whi, const __nv_bfloat16* __restrict__ Wlo,
    const float* __restrict__ blv, const float* __restrict__ brv,
    float* __restrict__ Cmat) {
    extern __shared__ uint8_t smem[];
    uint32_t sbase = (uint32_t)__cvta_generic_to_shared(smem);
    const int bcol = blockIdx.y * 128;  // within 512
    const int brow = blockIdx.x * 128;
    const int tid = threadIdx.x;
    const int lane = tid & 31;
    const int warp = tid >> 5;
    const int wm = warp >> 2;  // 0..1
    const int wn = warp & 3;   // 0..3

    float acc[4][4][4];
#pragma unroll
    for (int i = 0; i < 4; i++)
#pragma unroll
        for (int j = 0; j < 4; j++)
#pragma unroll
            for (int r = 0; r < 4; r++) acc[i][j][r] = 0.f;

    auto prefetch = [&](int kt, int soff) {
#pragma unroll
        for (int i = 0; i < 2; i++) {
            int c = tid + i * 256;
            int m = c >> 2, kc = c & 3;
            int grow = brow + m;
            int sz = (grow < Mrows) ? 16 : 0;
            uint32_t da = sbase + soff + (m * 4 + (kc ^ ((m >> 1) & 3))) * 16;
            size_t gofs = (size_t)grow * K + kt + kc * 8;
            cp_async16(da, Ahi + gofs, sz);
            cp_async16(da + 8192, Alo + gofs, sz);
        }
#pragma unroll
        for (int i = 0; i < 2; i++) {
            int c = tid + i * 256;
            int k = c >> 4, nc = c & 15;
            uint32_t db = sbase + soff + 16384 + (k * 16 + (nc ^ (k & 7))) * 16;
            size_t gofs = (size_t)(kt + k) * 512 + bcol + nc * 8;
            cp_async16(db, Whi + gofs, 16);
            cp_async16(db + 8192, Wlo + gofs, 16);
        }
        asm volatile("cp.async.commit_group;");
    };

    const int nk = K >> 5;
    prefetch(0, 0);
    asm volatile("cp.async.wait_group 0;");
    __syncthreads();

    const int lr = lane & 7;
    const int sel = lane >> 3;
    int buf = 0;
    for (int it = 0; it < nk; it++) {
        if (it + 1 < nk) prefetch((it + 1) << 5, (buf ^ 1) * 32768);
        int soff = buf * 32768;
#pragma unroll
        for (int s = 0; s < 2; s++) {
            uint32_t ah[4][4], al[4][4], bh[2][4], blo[2][4];
#pragma unroll
            for (int t = 0; t < 4; t++) {
                int m = wm * 64 + t * 16 + lr + ((sel & 1) << 3);
                int kc = s * 2 + ((sel >> 1) & 1);
                uint32_t addr = sbase + soff + (m * 4 + (kc ^ ((m >> 1) & 3))) * 16;
                ldsm_x4(ah[t], addr);
                ldsm_x4(al[t], addr + 8192);
            }
#pragma unroll
            for (int j2 = 0; j2 < 2; j2++) {
                int k = s * 16 + ((sel & 1) << 3) + lr;
                int nt = wn * 4 + 2 * j2 + ((sel >> 1) & 1);
                uint32_t addr = sbase + soff + 16384 + (k * 16 + (nt ^ (k & 7))) * 16;
                ldsm_x4_t(bh[j2], addr);
                ldsm_x4_t(blo[j2], addr + 8192);
            }
#pragma unroll
            for (int i = 0; i < 4; i++)
#pragma unroll
                for (int j = 0; j < 4; j++) {
                    const uint32_t* bp = &bh[j >> 1][(j & 1) * 2];
                    const uint32_t* blp = &blo[j >> 1][(j & 1) * 2];
                    mma_bf16(acc[i][j], ah[i], bp[0], bp[1]);
                    mma_bf16(acc[i][j], ah[i], blp[0], blp[1]);
                    mma_bf16(acc[i][j], al[i], bp[0], bp[1]);
                }
        }
        if (it + 1 < nk) asm volatile("cp.async.wait_group 0;");
        __syncthreads();
        buf ^= 1;
    }

    // epilogue: bias add + store
    int r0 = lane >> 2;
    int c0 = (lane & 3) * 2;
#pragma unroll
    for (int j = 0; j < 4; j++) {
        int gcol = bcol + wn * 32 + j * 8 + c0;
        float b0v = (gcol < 256) ? blv[gcol] : brv[gcol - 256];
        float b1v = (gcol < 256) ? blv[gcol + 1] : brv[gcol + 1 - 256];
#pragma unroll
        for (int i = 0; i < 4; i++) {
            int grow = brow + wm * 64 + i * 16 + r0;
            if (grow < Mrows) {
                float2 v = make_float2(acc[i][j][0] + b0v, acc[i][j][1] + b1v);
                *reinterpret_cast<float2*>(Cmat + (size_t)grow * 512 + gcol) = v;
            }
            if (grow + 8 < Mrows) {
                float2 v = make_float2(acc[i][j][2] + b0v, acc[i][j][3] + b1v);
                *reinterpret_cast<float2*>(Cmat + (size_t)(grow + 8) * 512 + gcol) = v;
            }
        }
    }
}

// ---------------- fused GATv2 node kernel ------------------------------------
// One warp per (node, head). No max-subtraction (softmax shift-invariant;
// logits are O(1) here), __expf, edge loop unrolled x2 to overlap the two
// shfl-reduce chains. Epilogue writes f32 (last layer) or bf16 hi/lo
// (feeding the next GEMM directly).
__global__ __launch_bounds__(256) void gat_node_kernel(
    const float* __restrict__ XLR,
    const int* __restrict__ rowptr, const int* __restrict__ perm,
    const int* __restrict__ src, const float* __restrict__ wgt,
    const float* __restrict__ att, const float* __restrict__ We,
    const float* __restrict__ bias,
    float* __restrict__ HoutF32,
    __nv_bfloat16* __restrict__ OutHi, __nv_bfloat16* __restrict__ OutLo) {
    int wid = (blockIdx.x * blockDim.x + threadIdx.x) >> 5;
    if (wid >= NN * 2) return;
    int lane = threadIdx.x & 31;
    int node = wid >> 1;
    int h = wid & 1;
    int base = h * CH + lane * 4;
    const float4 xr = *reinterpret_cast<const float4*>(XLR + (size_t)node * 512 + 256 + base);
    const float4 av = *reinterpret_cast<const float4*>(att + base);
    const float4 wv = *reinterpret_cast<const float4*>(We + base);
    float d = 0.f;
    float4 acc = make_float4(0.f, 0.f, 0.f, 0.f);
    int i0 = rowptr[node], i1 = rowptr[node + 1];
    float wmean = g_wmean;
    int idx = i0;
    for (; idx + 2 <= i1; idx += 2) {
        int e0 = perm[idx], e1 = perm[idx + 1];
        int s0 = src[e0], s1 = src[e1];
        float ea0 = (e0 < EE) ? __ldg(wgt + e0) : wmean;
        float ea1 = (e1 < EE) ? __ldg(wgt + e1) : wmean;
        float4 x0 = *reinterpret_cast<const float4*>(XLR + (size_t)s0 * 512 + base);
        float4 x1 = *reinterpret_cast<const float4*>(XLR + (size_t)s1 * 512 + base);
        float t0, t1, t2, t3, u0, u1, u2, u3;
        t0 = x0.x + xr.x + ea0 * wv.x; t1 = x0.y + xr.y + ea0 * wv.y;
        t2 = x0.z + xr.z + ea0 * wv.z; t3 = x0.w + xr.w + ea0 * wv.w;
        u0 = x1.x + xr.x + ea1 * wv.x; u1 = x1.y + xr.y + ea1 * wv.y;
        u2 = x1.z + xr.z + ea1 * wv.z; u3 = x1.w + xr.w + ea1 * wv.w;
        t0 = t0 > 0.f ? t0 : 0.2f * t0; t1 = t1 > 0.f ? t1 : 0.2f * t1;
        t2 = t2 > 0.f ? t2 : 0.2f * t2; t3 = t3 > 0.f ? t3 : 0.2f * t3;
        u0 = u0 > 0.f ? u0 : 0.2f * u0; u1 = u1 > 0.f ? u1 : 0.2f * u1;
        u2 = u2 > 0.f ? u2 : 0.2f * u2; u3 = u3 > 0.f ? u3 : 0.2f * u3;
        float p0 = t0 * av.x + t1 * av.y + t2 * av.z + t3 * av.w;
        float p1 = u0 * av.x + u1 * av.y + u2 * av.z + u3 * av.w;
#pragma unroll
        for (int off = 16; off >= 1; off >>= 1) {
            p0 += __shfl_xor_sync(0xffffffffu, p0, off);
            p1 += __shfl_xor_sync(0xffffffffu, p1, off);
        }
        float pe0 = __expf(p0);
        float pe1 = __expf(p1);
        d += pe0 + pe1;
        acc.x += pe0 * x0.x + pe1 * x1.x;
        acc.y += pe0 * x0.y + pe1 * x1.y;
        acc.z += pe0 * x0.z + pe1 * x1.z;
        acc.w += pe0 * x0.w + pe1 * x1.w;
    }
    if (idx < i1) {
        int e = perm[idx];
        int s = src[e];
        float ea = (e < EE) ? __ldg(wgt + e) : wmean;
        float4 xl = *reinterpret_cast<const float4*>(XLR + (size_t)s * 512 + base);
        float t0 = xl.x + xr.x + ea * wv.x;
        float t1 = xl.y + xr.y + ea * wv.y;
        float t2 = xl.z + xr.z + ea * wv.z;
        float t3 = xl.w + xr.w + ea * wv.w;
        t0 = t0 > 0.f ? t0 : 0.2f * t0; t1 = t1 > 0.f ? t1 : 0.2f * t1;
        t2 = t2 > 0.f ? t2 : 0.2f * t2; t3 = t3 > 0.f ? t3 : 0.2f * t3;
        float p = t0 * av.x + t1 * av.y + t2 * av.z + t3 * av.w;
#pragma unroll
        for (int off = 16; off >= 1; off >>= 1) p += __shfl_xor_sync(0xffffffffu, p, off);
        float pe = __expf(p);
        d += pe;
        acc.x += pe * xl.x;
        acc.y += pe * xl.y;
        acc.z += pe * xl.z;
        acc.w += pe * xl.w;
    }
    float inv = (i1 > i0) ? 1.f / (d + 1e-16f) : 0.f;
    const float4 bv = *reinterpret_cast<const float4*>(bias + base);
    float o0 = acc.x * inv + bv.x;
    float o1 = acc.y * inv + bv.y;
    float o2 = acc.z * inv + bv.z;
    float o3 = acc.w * inv + bv.w;
    o0 = o0 > 0.f ? o0 : expm1f(o0);
    o1 = o1 > 0.f ? o1 : expm1f(o1);
    o2 = o2 > 0.f ? o2 : expm1f(o2);
    o3 = o3 > 0.f ? o3 : expm1f(o3);
    if (HoutF32) {
        *reinterpret_cast<float4*>(HoutF32 + (size_t)node * HC + base) =
            make_float4(o0, o1, o2, o3);
    } else {
        __nv_bfloat16 h0, h1, h2, h3, l0, l1, l2, l3;
        split_bf16(o0, h0, l0); split_bf16(o1, h1, l1);
        split_bf16(o2, h2, l2); split_bf16(o3, h3, l3);
        size_t ofs = (size_t)node * HC + base;
        *reinterpret_cast<uint2*>(OutHi + ofs) = make_uint2(pack_bf16(h0, h1), pack_bf16(h2, h3));
        *reinterpret_cast<uint2*>(OutLo + ofs) = make_uint2(pack_bf16(l0, l1), pack_bf16(l2, l3));
    }
}

// ---------------- final classifier ------------------------------------------
__global__ __launch_bounds__(256) void fc_kernel(const float* __restrict__ Hin,
                                                 const float* __restrict__ W,
                                                 const float* __restrict__ b,
                                                 float* __restrict__ out) {
    int wid = (blockIdx.x * blockDim.x + threadIdx.x) >> 5;
    if (wid >= NN) return;
    int lane = threadIdx.x & 31;
    float acc[NCLASS];
#pragma unroll
    for (int k = 0; k < NCLASS; k++) acc[k] = 0.f;
#pragma unroll
    for (int j0 = 0; j0 < HC; j0 += 32) {
        float hv = Hin[(size_t)wid * HC + j0 + lane];
        const float* wr = W + (size_t)(j0 + lane) * NCLASS;
#pragma unroll
        for (int k = 0; k < NCLASS; k++) acc[k] += hv * __ldg(wr + k);
    }
#pragma unroll
    for (int k = 0; k < NCLASS; k++) {
#pragma unroll
        for (int off = 16; off >= 1; off >>= 1)
            acc[k] += __shfl_xor_sync(0xffffffffu, acc[k], off);
    }
    if (lane == 0) {
#pragma unroll
        for (int k = 0; k < NCLASS; k++) out[(size_t)wid * NCLASS + k] = acc[k] + b[k];
    }
}

// ---------------- launch -----------------------------------------------------
extern "C" void kernel_launch(void* const* d_in, const int* in_sizes, int n_in,
                              void* d_out, int out_size) {
    const float* x = (const float*)d_in[0];
    const void* ei = d_in[1];
    const float* wgt = (const float*)d_in[2];
    const float *Wl[3], *bl[3], *Wr[3], *br[3], *We[3], *att[3], *bb[3];
    for (int i = 0; i < 3; i++) {
        int bse = 3 + 7 * i;
        Wl[i] = (const float*)d_in[bse + 0];
        bl[i] = (const float*)d_in[bse + 1];
        Wr[i] = (const float*)d_in[bse + 2];
        br[i] = (const float*)d_in[bse + 3];
        We[i] = (const float*)d_in[bse + 4];
        att[i] = (const float*)d_in[bse + 5];
        bb[i] = (const float*)d_in[bse + 6];
    }
    const float* fcW = (const float*)d_in[24];
    const float* fcb = (const float*)d_in[25];
    float* out = (float*)d_out;

    int *psrc, *pdst, *pcnt, *pcursor, *prow0, *prow1, *pperm0, *pperm1;
    float *pXLR, *pHA;
    __nv_bfloat16 *pAhi, *pAlo, *pWhi, *pWlo;
    cudaGetSymbolAddress((void**)&psrc, g_src);
    cudaGetSymbolAddress((void**)&pdst, g_dst);
    cudaGetSymbolAddress((void**)&pcnt, g_cnt);
    cudaGetSymbolAddress((void**)&pcursor, g_cursor);
    cudaGetSymbolAddress((void**)&prow0, g_rowptr0);
    cudaGetSymbolAddress((void**)&prow1, g_rowptr1);
    cudaGetSymbolAddress((void**)&pperm0, g_perm0);
    cudaGetSymbolAddress((void**)&pperm1, g_perm1);
    cudaGetSymbolAddress((void**)&pXLR, g_XLR);
    cudaGetSymbolAddress((void**)&pHA, g_HA);
    cudaGetSymbolAddress((void**)&pAhi, g_Ahi);
    cudaGetSymbolAddress((void**)&pAlo, g_Alo);
    cudaGetSymbolAddress((void**)&pWhi, g_Whi);
    cudaGetSymbolAddress((void**)&pWlo, g_Wlo);

    cudaFuncSetAttribute(gemm_bf16_ldsm_kernel,
                         cudaFuncAttributeMaxDynamicSharedMemorySize, 65536);

    // edge decode + self loops, weight mean
    convert_edges_kernel<<<(ESLN + 255) / 256, 256>>>((const unsigned int*)ei, psrc, pdst);
    mean_partial_kernel<<<256, 256>>>(wgt);
    mean_final_kernel<<<1, 256>>>();

    // CSR 0 (no self loops, layer 0)
    zero_int_kernel<<<(NN + 255) / 256, 256>>>(pcnt, NN);
    hist_kernel<<<(EE + 255) / 256, 256>>>(pdst, pcnt, EE);
    scan_local_kernel<<<NB0, 1024>>>(pcnt, prow0);
    scan_bsum_kernel<<<1, 64>>>(prow0);
    scan_add_kernel<<<NB0, 1024>>>(prow0, pcursor);
    scatter_kernel<<<(EE + 255) / 256, 256>>>(pdst, pcursor, pperm0, EE);
    // CSR 1 (with self loops, layers 1-2)
    zero_int_kernel<<<(NN + 255) / 256, 256>>>(pcnt, NN);
    hist_kernel<<<(ESLN + 255) / 256, 256>>>(pdst, pcnt, ESLN);
    scan_local_kernel<<<NB0, 1024>>>(pcnt, prow1);
    scan_bsum_kernel<<<1, 64>>>(prow1);
    scan_add_kernel<<<NB0, 1024>>>(prow1, pcursor);
    scatter_kernel<<<(ESLN + 255) / 256, 256>>>(pdst, pcursor, pperm1, ESLN);

    // weights -> bf16 hi/lo (combined [K,512] per layer)
    w_convert_kernel<<<(640 * 512 + 255) / 256, 256>>>(Wl[0], Wr[0], Wl[1], Wr[1], Wl[2], Wr[2]);
    // x -> bf16 hi/lo
    a_convert_kernel<<<(NN * FIN / 4 + 255) / 256, 256>>>(x, pAhi, pAlo, NN * FIN);

    dim3 ggrid((NN + 127) / 128, 4);
    int node_blocks = (NN * 2 * 32 + 255) / 256;

    // Layer 0
    gemm_bf16_ldsm_kernel<<<ggrid, 256, 65536>>>(pAhi, pAlo, NN, FIN,
                                                 pWhi, pWlo, bl[0], br[0], pXLR);
    gat_node_kernel<<<node_blocks, 256>>>(pXLR, prow0, pperm0, psrc, wgt,
                                          att[0], We[0], bb[0],
                                          nullptr, pAhi, pAlo);
    // Layer 1
    gemm_bf16_ldsm_kernel<<<ggrid, 256, 65536>>>(pAhi, pAlo, NN, HC,
                                                 pWhi + 128 * 512, pWlo + 128 * 512,
                                                 bl[1], br[1], pXLR);
    gat_node_kernel<<<node_blocks, 256>>>(pXLR, prow1, pperm1, psrc, wgt,
                                          att[1], We[1], bb[1],
                                          nullptr, pAhi, pAlo);
    // Layer 2
    gemm_bf16_ldsm_kernel<<<ggrid, 256, 65536>>>(pAhi, pAlo, NN, HC,
                                                 pWhi + 384 * 512, pWlo + 384 * 512,
                                                 bl[2], br[2], pXLR);
    gat_node_kernel<<<node_blocks, 256>>>(pXLR, prow1, pperm1, psrc, wgt,
                                          att[2], We[2], bb[2],
                                          pHA, nullptr, nullptr);
    // Classifier
    fc_kernel<<<(NN * 32 + 255) / 256, 256>>>(pHA, fcW, fcb, out);
}

// round 6
// speedup vs baseline: 3.0586x; 1.0651x over previous
#include <cuda_runtime.h>
#include <cuda_bf16.h>
#include <math.h>
#include <stdint.h>

#define NN 50000
#define EE 500000
#define ESLN 550000   // EE + NN (edges with self loops)
#define FIN 128
#define HC 256
#define CH 128
#define NCLASS 10
#define NB0 49        // ceil(NN/1024)

// ---------------- scratch (static __device__ globals; no allocation) -------
__device__ int   g_src[ESLN];
__device__ int   g_dst[ESLN];
__device__ int   g_cnt[NN];
__device__ int   g_cursor[NN];
__device__ int   g_rowptr1[NN + 1];
__device__ int   g_perm1[ESLN];
__device__ float g_XLR[(size_t)NN * 512];   // [N,512]: 0..255 = xl, 256..511 = xr
__device__ float g_HA[(size_t)NN * HC];     // final layer f32 output
__device__ __nv_bfloat16 g_Ahi[(size_t)NN * HC];
__device__ __nv_bfloat16 g_Alo[(size_t)NN * HC];
__device__ __nv_bfloat16 g_Whi[640 * 512];  // layer0 rows 0-127, l1 128-383, l2 384-639
__device__ __nv_bfloat16 g_Wlo[640 * 512];
__device__ float g_partial[256];
__device__ float g_wmean;
__device__ int   g_bsum[64];

// ---------------- small utility kernels ------------------------------------
__global__ void zero_int_kernel(int* p, int n) {
    int i = blockIdx.x * blockDim.x + threadIdx.x;
    if (i < n) p[i] = 0;
}

// edge_index may be int32 or int64 depending on JAX x64 config.
__global__ void convert_edges_kernel(const unsigned int* __restrict__ ei,
                                     int* __restrict__ src, int* __restrict__ dst) {
    __shared__ int s_is64;
    if (threadIdx.x == 0) {
        unsigned int acc = 0;
#pragma unroll
        for (int k = 0; k < 32; k++) acc |= ei[2 * k + 1];
        s_is64 = (acc == 0u) ? 1 : 0;
    }
    __syncthreads();
    int is64 = s_is64;
    int i = blockIdx.x * blockDim.x + threadIdx.x;
    if (i >= ESLN) return;
    if (i < EE) {
        int s, d;
        if (is64) {
            const long long* p = reinterpret_cast<const long long*>(ei);
            s = (int)p[i];
            d = (int)p[EE + i];
        } else {
            const int* p = reinterpret_cast<const int*>(ei);
            s = p[i];
            d = p[EE + i];
        }
        src[i] = s;
        dst[i] = d;
    } else {
        int v = i - EE;
        src[i] = v;
        dst[i] = v;
    }
}

__global__ void mean_partial_kernel(const float* __restrict__ w) {
    __shared__ float s[256];
    float acc = 0.f;
    for (int i = blockIdx.x * 256 + threadIdx.x; i < EE; i += 256 * 256) acc += w[i];
    s[threadIdx.x] = acc;
    __syncthreads();
    for (int off = 128; off > 0; off >>= 1) {
        if (threadIdx.x < off) s[threadIdx.x] += s[threadIdx.x + off];
        __syncthreads();
    }
    if (threadIdx.x == 0) g_partial[blockIdx.x] = s[0];
}

__global__ void mean_final_kernel() {
    __shared__ float s[256];
    s[threadIdx.x] = g_partial[threadIdx.x];
    __syncthreads();
    for (int off = 128; off > 0; off >>= 1) {
        if (threadIdx.x < off) s[threadIdx.x] += s[threadIdx.x + off];
        __syncthreads();
    }
    if (threadIdx.x == 0) g_wmean = s[0] / (float)EE;
}

__global__ void hist_kernel(const int* __restrict__ dst, int* __restrict__ cnt, int count) {
    int e = blockIdx.x * blockDim.x + threadIdx.x;
    if (e < count) atomicAdd(&cnt[dst[e]], 1);
}

// ---- 3-phase scan ----
__global__ void scan_local_kernel(const int* __restrict__ cnt, int* __restrict__ rowptr) {
    __shared__ int s[1024];
    int t = threadIdx.x;
    int i = blockIdx.x * 1024 + t;
    int v = (i < NN) ? cnt[i] : 0;
    s[t] = v;
    __syncthreads();
    for (int off = 1; off < 1024; off <<= 1) {
        int x = s[t];
        int y = (t >= off) ? s[t - off] : 0;
        __syncthreads();
        s[t] = x + y;
        __syncthreads();
    }
    if (i < NN) rowptr[i] = s[t] - v;
    if (t == 1023) g_bsum[blockIdx.x] = s[1023];
}

__global__ void scan_bsum_kernel(int* __restrict__ rowptr) {
    __shared__ int s[64];
    int t = threadIdx.x;
    int v = (t < NB0) ? g_bsum[t] : 0;
    s[t] = v;
    __syncthreads();
    for (int off = 1; off < 64; off <<= 1) {
        int x = s[t];
        int y = (t >= off) ? s[t - off] : 0;
        __syncthreads();
        s[t] = x + y;
        __syncthreads();
    }
    if (t < NB0) g_bsum[t] = s[t] - v;
    if (t == 63) rowptr[NN] = s[63];
}

__global__ void scan_add_kernel(int* __restrict__ rowptr, int* __restrict__ cursor) {
    int i = blockIdx.x * 1024 + threadIdx.x;
    if (i < NN) {
        int r = rowptr[i] + g_bsum[blockIdx.x];
        rowptr[i] = r;
        cursor[i] = r;
    }
}

__global__ void scatter_kernel(const int* __restrict__ dst, int* __restrict__ cursor,
                               int* __restrict__ perm, int count) {
    int e = blockIdx.x * blockDim.x + threadIdx.x;
    if (e < count) {
        int p = atomicAdd(&cursor[dst[e]], 1);
        perm[p] = e;
    }
}

// ---------------- bf16 helpers ----------------------------------------------
__device__ __forceinline__ uint32_t pack_bf16(__nv_bfloat16 a, __nv_bfloat16 b) {
    __nv_bfloat162 t = __halves2bfloat162(a, b);
    return *reinterpret_cast<uint32_t*>(&t);
}

__device__ __forceinline__ void split_bf16(float x, __nv_bfloat16& h, __nv_bfloat16& l) {
    h = __float2bfloat16_rn(x);
    l = __float2bfloat16_rn(x - __bfloat162float(h));
}

__device__ __forceinline__ void mma_bf16(float* c, const uint32_t* a, uint32_t b0, uint32_t b1) {
    asm volatile(
        "mma.sync.aligned.m16n8k16.row.col.f32.bf16.bf16.f32 "
        "{%0,%1,%2,%3}, {%4,%5,%6,%7}, {%8,%9}, {%0,%1,%2,%3};"
        : "+f"(c[0]), "+f"(c[1]), "+f"(c[2]), "+f"(c[3])
        : "r"(a[0]), "r"(a[1]), "r"(a[2]), "r"(a[3]), "r"(b0), "r"(b1));
}

__device__ __forceinline__ void ldsm_x4(uint32_t* r, uint32_t saddr) {
    asm volatile("ldmatrix.sync.aligned.m8n8.x4.shared.b16 {%0,%1,%2,%3}, [%4];"
                 : "=r"(r[0]), "=r"(r[1]), "=r"(r[2]), "=r"(r[3]) : "r"(saddr));
}

__device__ __forceinline__ void ldsm_x4_t(uint32_t* r, uint32_t saddr) {
    asm volatile("ldmatrix.sync.aligned.m8n8.x4.trans.shared.b16 {%0,%1,%2,%3}, [%4];"
                 : "=r"(r[0]), "=r"(r[1]), "=r"(r[2]), "=r"(r[3]) : "r"(saddr));
}

__device__ __forceinline__ void cp_async16(uint32_t saddr, const void* g, int sz) {
    asm volatile("cp.async.cg.shared.global [%0], [%1], 16, %2;"
                 :: "r"(saddr), "l"(g), "r"(sz));
}

// ---------------- conversion kernels ----------------------------------------
__global__ void a_convert_kernel(const float* __restrict__ A,
                                 __nv_bfloat16* __restrict__ hi,
                                 __nv_bfloat16* __restrict__ lo, int total) {
    int i = (blockIdx.x * blockDim.x + threadIdx.x) * 4;
    if (i >= total) return;
    float4 v = *reinterpret_cast<const float4*>(A + i);
    __nv_bfloat16 h0, h1, h2, h3, l0, l1, l2, l3;
    split_bf16(v.x, h0, l0); split_bf16(v.y, h1, l1);
    split_bf16(v.z, h2, l2); split_bf16(v.w, h3, l3);
    *reinterpret_cast<uint2*>(hi + i) = make_uint2(pack_bf16(h0, h1), pack_bf16(h2, h3));
    *reinterpret_cast<uint2*>(lo + i) = make_uint2(pack_bf16(l0, l1), pack_bf16(l2, l3));
}

__global__ void w_convert_kernel(const float* __restrict__ Wl0, const float* __restrict__ Wr0,
                                 const float* __restrict__ Wl1, const float* __restrict__ Wr1,
                                 const float* __restrict__ Wl2, const float* __restrict__ Wr2) {
    int i = blockIdx.x * blockDim.x + threadIdx.x;
    if (i >= 640 * 512) return;
    int row = i >> 9, col = i & 511;
    const float *Wl, *Wr;
    int k;
    if (row < 128) { Wl = Wl0; Wr = Wr0; k = row; }
    else if (row < 384) { Wl = Wl1; Wr = Wr1; k = row - 128; }
    else { Wl = Wl2; Wr = Wr2; k = row - 384; }
    float v = (col < 256) ? Wl[k * 256 + col] : Wr[k * 256 + col - 256];
    __nv_bfloat16 h, l;
    split_bf16(v, h, l);
    g_Whi[i] = h;
    g_Wlo[i] = l;
}

// ---------------- GEMM: C[N,512] = A[N,K] @ W + bias -----------------------
// Grid is (4 col-strips, rowTiles): consecutive blocks share the A row tile,
// so A streams from DRAM ~once per GEMM instead of 4x.
__global__ __launch_bounds__(256) void gemm_bf16_ldsm_kernel(
    const __nv_bfloat16* __restrict__ Ahi, const __nv_bfloat16* __restrict__ Alo,
    int Mrows, int K,
    const __nv_bfloat16* __restrict__ Whi, const __nv_bfloat16* __restrict__ Wlo,
    const float* __restrict__ blv, const float* __restrict__ brv,
    float* __restrict__ Cmat) {
    extern __shared__ uint8_t smem[];
    uint32_t sbase = (uint32_t)__cvta_generic_to_shared(smem);
    const int bcol = blockIdx.x * 128;  // within 512
    const int brow = blockIdx.y * 128;
    const int tid = threadIdx.x;
    const int lane = tid & 31;
    const int warp = tid >> 5;
    const int wm = warp >> 2;  // 0..1
    const int wn = warp & 3;   // 0..3

    float acc[4][4][4];
#pragma unroll
    for (int i = 0; i < 4; i++)
#pragma unroll
        for (int j = 0; j < 4; j++)
#pragma unroll
            for (int r = 0; r < 4; r++) acc[i][j][r] = 0.f;

    auto prefetch = [&](int kt, int soff) {
#pragma unroll
        for (int i = 0; i < 2; i++) {
            int c = tid + i * 256;
            int m = c >> 2, kc = c & 3;
            int grow = brow + m;
            int sz = (grow < Mrows) ? 16 : 0;
            uint32_t da = sbase + soff + (m * 4 + (kc ^ ((m >> 1) & 3))) * 16;
            size_t gofs = (size_t)grow * K + kt + kc * 8;
            cp_async16(da, Ahi + gofs, sz);
            cp_async16(da + 8192, Alo + gofs, sz);
        }
#pragma unroll
        for (int i = 0; i < 2; i++) {
            int c = tid + i * 256;
            int k = c >> 4, nc = c & 15;
            uint32_t db = sbase + soff + 16384 + (k * 16 + (nc ^ (k & 7))) * 16;
            size_t gofs = (size_t)(kt + k) * 512 + bcol + nc * 8;
            cp_async16(db, Whi + gofs, 16);
            cp_async16(db + 8192, Wlo + gofs, 16);
        }
        asm volatile("cp.async.commit_group;");
    };

    const int nk = K >> 5;
    prefetch(0, 0);
    asm volatile("cp.async.wait_group 0;");
    __syncthreads();

    const int lr = lane & 7;
    const int sel = lane >> 3;
    int buf = 0;
    for (int it = 0; it < nk; it++) {
        if (it + 1 < nk) prefetch((it + 1) << 5, (buf ^ 1) * 32768);
        int soff = buf * 32768;
#pragma unroll
        for (int s = 0; s < 2; s++) {
            uint32_t ah[4][4], al[4][4], bh[2][4], blo[2][4];
#pragma unroll
            for (int t = 0; t < 4; t++) {
                int m = wm * 64 + t * 16 + lr + ((sel & 1) << 3);
                int kc = s * 2 + ((sel >> 1) & 1);
                uint32_t addr = sbase + soff + (m * 4 + (kc ^ ((m >> 1) & 3))) * 16;
                ldsm_x4(ah[t], addr);
                ldsm_x4(al[t], addr + 8192);
            }
#pragma unroll
            for (int j2 = 0; j2 < 2; j2++) {
                int k = s * 16 + ((sel & 1) << 3) + lr;
                int nt = wn * 4 + 2 * j2 + ((sel >> 1) & 1);
                uint32_t addr = sbase + soff + 16384 + (k * 16 + (nt ^ (k & 7))) * 16;
                ldsm_x4_t(bh[j2], addr);
                ldsm_x4_t(blo[j2], addr + 8192);
            }
#pragma unroll
            for (int i = 0; i < 4; i++)
#pragma unroll
                for (int j = 0; j < 4; j++) {
                    const uint32_t* bp = &bh[j >> 1][(j & 1) * 2];
                    const uint32_t* blp = &blo[j >> 1][(j & 1) * 2];
                    mma_bf16(acc[i][j], ah[i], bp[0], bp[1]);
                    mma_bf16(acc[i][j], ah[i], blp[0], blp[1]);
                    mma_bf16(acc[i][j], al[i], bp[0], bp[1]);
                }
        }
        if (it + 1 < nk) asm volatile("cp.async.wait_group 0;");
        __syncthreads();
        buf ^= 1;
    }

    // epilogue: bias add + store
    int r0 = lane >> 2;
    int c0 = (lane & 3) * 2;
#pragma unroll
    for (int j = 0; j < 4; j++) {
        int gcol = bcol + wn * 32 + j * 8 + c0;
        float b0v = (gcol < 256) ? blv[gcol] : brv[gcol - 256];
        float b1v = (gcol < 256) ? blv[gcol + 1] : brv[gcol + 1 - 256];
#pragma unroll
        for (int i = 0; i < 4; i++) {
            int grow = brow + wm * 64 + i * 16 + r0;
            if (grow < Mrows) {
                float2 v = make_float2(acc[i][j][0] + b0v, acc[i][j][1] + b1v);
                *reinterpret_cast<float2*>(Cmat + (size_t)grow * 512 + gcol) = v;
            }
            if (grow + 8 < Mrows) {
                float2 v = make_float2(acc[i][j][2] + b0v, acc[i][j][3] + b1v);
                *reinterpret_cast<float2*>(Cmat + (size_t)(grow + 8) * 512 + gcol) = v;
            }
        }
    }
}

// ---------------- fused GATv2 node kernel ------------------------------------
// One warp per (node, head); iterates CSR-with-self-loops. skipSelf=1 (layer0)
// masks self-loop edges (mask multiply, no divergence). Edge loop unrolled x4
// for gather MLP. Epilogue: bias+ELU -> f32 (last layer) or bf16 hi/lo.
__global__ __launch_bounds__(256) void gat_node_kernel(
    const float* __restrict__ XLR,
    const int* __restrict__ rowptr, const int* __restrict__ perm,
    const int* __restrict__ src, const float* __restrict__ wgt,
    const float* __restrict__ att, const float* __restrict__ We,
    const float* __restrict__ bias, int skipSelf,
    float* __restrict__ HoutF32,
    __nv_bfloat16* __restrict__ OutHi, __nv_bfloat16* __restrict__ OutLo) {
    int wid = (blockIdx.x * blockDim.x + threadIdx.x) >> 5;
    if (wid >= NN * 2) return;
    int lane = threadIdx.x & 31;
    int node = wid >> 1;
    int h = wid & 1;
    int base = h * CH + lane * 4;
    const float4 xr = *reinterpret_cast<const float4*>(XLR + (size_t)node * 512 + 256 + base);
    const float4 av = *reinterpret_cast<const float4*>(att + base);
    const float4 wv = *reinterpret_cast<const float4*>(We + base);
    float d = 0.f;
    float4 acc = make_float4(0.f, 0.f, 0.f, 0.f);
    int i0 = rowptr[node], i1 = rowptr[node + 1];
    float wmean = g_wmean;
    int idx = i0;
#define EDGE_BODY(eV, peV)                                                     \
    {                                                                          \
        int s_ = src[eV];                                                      \
        float ea_ = (eV < EE) ? __ldg(wgt + eV) : wmean;                       \
        float4 xl_ = *reinterpret_cast<const float4*>(XLR + (size_t)s_ * 512 + base); \
        float q0 = xl_.x + xr.x + ea_ * wv.x;                                  \
        float q1 = xl_.y + xr.y + ea_ * wv.y;                                  \
        float q2 = xl_.z + xr.z + ea_ * wv.z;                                  \
        float q3 = xl_.w + xr.w + ea_ * wv.w;                                  \
        q0 = q0 > 0.f ? q0 : 0.2f * q0;                                        \
        q1 = q1 > 0.f ? q1 : 0.2f * q1;                                        \
        q2 = q2 > 0.f ? q2 : 0.2f * q2;                                        \
        q3 = q3 > 0.f ? q3 : 0.2f * q3;                                        \
        peV = q0 * av.x + q1 * av.y + q2 * av.z + q3 * av.w;                   \
        xsave = xl_;                                                           \
    }
    for (; idx + 4 <= i1; idx += 4) {
        int e0 = perm[idx], e1 = perm[idx + 1], e2 = perm[idx + 2], e3 = perm[idx + 3];
        float p0, p1, p2, p3;
        float4 xsave;
        float4 x0, x1, x2, x3;
        EDGE_BODY(e0, p0); x0 = xsave;
        EDGE_BODY(e1, p1); x1 = xsave;
        EDGE_BODY(e2, p2); x2 = xsave;
        EDGE_BODY(e3, p3); x3 = xsave;
#pragma unroll
        for (int off = 16; off >= 1; off >>= 1) {
            p0 += __shfl_xor_sync(0xffffffffu, p0, off);
            p1 += __shfl_xor_sync(0xffffffffu, p1, off);
            p2 += __shfl_xor_sync(0xffffffffu, p2, off);
            p3 += __shfl_xor_sync(0xffffffffu, p3, off);
        }
        float m0 = (skipSelf && e0 >= EE) ? 0.f : 1.f;
        float m1 = (skipSelf && e1 >= EE) ? 0.f : 1.f;
        float m2 = (skipSelf && e2 >= EE) ? 0.f : 1.f;
        float m3 = (skipSelf && e3 >= EE) ? 0.f : 1.f;
        float pe0 = __expf(p0) * m0, pe1 = __expf(p1) * m1;
        float pe2 = __expf(p2) * m2, pe3 = __expf(p3) * m3;
        d += (pe0 + pe1) + (pe2 + pe3);
        acc.x += pe0 * x0.x + pe1 * x1.x + pe2 * x2.x + pe3 * x3.x;
        acc.y += pe0 * x0.y + pe1 * x1.y + pe2 * x2.y + pe3 * x3.y;
        acc.z += pe0 * x0.z + pe1 * x1.z + pe2 * x2.z + pe3 * x3.z;
        acc.w += pe0 * x0.w + pe1 * x1.w + pe2 * x2.w + pe3 * x3.w;
    }
    for (; idx < i1; idx++) {
        int e = perm[idx];
        float p;
        float4 xsave;
        EDGE_BODY(e, p);
#pragma unroll
        for (int off = 16; off >= 1; off >>= 1) p += __shfl_xor_sync(0xffffffffu, p, off);
        float m = (skipSelf && e >= EE) ? 0.f : 1.f;
        float pe = __expf(p) * m;
        d += pe;
        acc.x += pe * xsave.x;
        acc.y += pe * xsave.y;
        acc.z += pe * xsave.z;
        acc.w += pe * xsave.w;
    }
#undef EDGE_BODY
    float inv = (d > 0.f) ? 1.f / (d + 1e-16f) : 0.f;
    const float4 bv = *reinterpret_cast<const float4*>(bias + base);
    float o0 = acc.x * inv + bv.x;
    float o1 = acc.y * inv + bv.y;
    float o2 = acc.z * inv + bv.z;
    float o3 = acc.w * inv + bv.w;
    o0 = o0 > 0.f ? o0 : expm1f(o0);
    o1 = o1 > 0.f ? o1 : expm1f(o1);
    o2 = o2 > 0.f ? o2 : expm1f(o2);
    o3 = o3 > 0.f ? o3 : expm1f(o3);
    if (HoutF32) {
        *reinterpret_cast<float4*>(HoutF32 + (size_t)node * HC + base) =
            make_float4(o0, o1, o2, o3);
    } else {
        __nv_bfloat16 h0, h1, h2, h3, l0, l1, l2, l3;
        split_bf16(o0, h0, l0); split_bf16(o1, h1, l1);
        split_bf16(o2, h2, l2); split_bf16(o3, h3, l3);
        size_t ofs = (size_t)node * HC + base;
        *reinterpret_cast<uint2*>(OutHi + ofs) = make_uint2(pack_bf16(h0, h1), pack_bf16(h2, h3));
        *reinterpret_cast<uint2*>(OutLo + ofs) = make_uint2(pack_bf16(l0, l1), pack_bf16(l2, l3));
    }
}

// ---------------- final classifier ------------------------------------------
__global__ __launch_bounds__(256) void fc_kernel(const float* __restrict__ Hin,
                                                 const float* __restrict__ W,
                                                 const float* __restrict__ b,
                                                 float* __restrict__ out) {
    int wid = (blockIdx.x * blockDim.x + threadIdx.x) >> 5;
    if (wid >= NN) return;
    int lane = threadIdx.x & 31;
    float acc[NCLASS];
#pragma unroll
    for (int k = 0; k < NCLASS; k++) acc[k] = 0.f;
#pragma unroll
    for (int j0 = 0; j0 < HC; j0 += 32) {
        float hv = Hin[(size_t)wid * HC + j0 + lane];
        const float* wr = W + (size_t)(j0 + lane) * NCLASS;
#pragma unroll
        for (int k = 0; k < NCLASS; k++) acc[k] += hv * __ldg(wr + k);
    }
#pragma unroll
    for (int k = 0; k < NCLASS; k++) {
#pragma unroll
        for (int off = 16; off >= 1; off >>= 1)
            acc[k] += __shfl_xor_sync(0xffffffffu, acc[k], off);
    }
    if (lane == 0) {
#pragma unroll
        for (int k = 0; k < NCLASS; k++) out[(size_t)wid * NCLASS + k] = acc[k] + b[k];
    }
}

// ---------------- launch -----------------------------------------------------
extern "C" void kernel_launch(void* const* d_in, const int* in_sizes, int n_in,
                              void* d_out, int out_size) {
    const float* x = (const float*)d_in[0];
    const void* ei = d_in[1];
    const float* wgt = (const float*)d_in[2];
    const float *Wl[3], *bl[3], *Wr[3], *br[3], *We[3], *att[3], *bb[3];
    for (int i = 0; i < 3; i++) {
        int bse = 3 + 7 * i;
        Wl[i] = (const float*)d_in[bse + 0];
        bl[i] = (const float*)d_in[bse + 1];
        Wr[i] = (const float*)d_in[bse + 2];
        br[i] = (const float*)d_in[bse + 3];
        We[i] = (const float*)d_in[bse + 4];
        att[i] = (const float*)d_in[bse + 5];
        bb[i] = (const float*)d_in[bse + 6];
    }
    const float* fcW = (const float*)d_in[24];
    const float* fcb = (const float*)d_in[25];
    float* out = (float*)d_out;

    int *psrc, *pdst, *pcnt, *pcursor, *prow1, *pperm1;
    float *pXLR, *pHA;
    __nv_bfloat16 *pAhi, *pAlo, *pWhi, *pWlo;
    cudaGetSymbolAddress((void**)&psrc, g_src);
    cudaGetSymbolAddress((void**)&pdst, g_dst);
    cudaGetSymbolAddress((void**)&pcnt, g_cnt);
    cudaGetSymbolAddress((void**)&pcursor, g_cursor);
    cudaGetSymbolAddress((void**)&prow1, g_rowptr1);
    cudaGetSymbolAddress((void**)&pperm1, g_perm1);
    cudaGetSymbolAddress((void**)&pXLR, g_XLR);
    cudaGetSymbolAddress((void**)&pHA, g_HA);
    cudaGetSymbolAddress((void**)&pAhi, g_Ahi);
    cudaGetSymbolAddress((void**)&pAlo, g_Alo);
    cudaGetSymbolAddress((void**)&pWhi, g_Whi);
    cudaGetSymbolAddress((void**)&pWlo, g_Wlo);

    cudaFuncSetAttribute(gemm_bf16_ldsm_kernel,
                         cudaFuncAttributeMaxDynamicSharedMemorySize, 65536);

    // edge decode + self loops, weight mean
    convert_edges_kernel<<<(ESLN + 255) / 256, 256>>>((const unsigned int*)ei, psrc, pdst);
    mean_partial_kernel<<<256, 256>>>(wgt);
    mean_final_kernel<<<1, 256>>>();

    // single CSR (with self loops) — layer 0 masks self loops at runtime
    zero_int_kernel<<<(NN + 255) / 256, 256>>>(pcnt, NN);
    hist_kernel<<<(ESLN + 255) / 256, 256>>>(pdst, pcnt, ESLN);
    scan_local_kernel<<<NB0, 1024>>>(pcnt, prow1);
    scan_bsum_kernel<<<1, 64>>>(prow1);
    scan_add_kernel<<<NB0, 1024>>>(prow1, pcursor);
    scatter_kernel<<<(ESLN + 255) / 256, 256>>>(pdst, pcursor, pperm1, ESLN);

    // weights -> bf16 hi/lo; x -> bf16 hi/lo
    w_convert_kernel<<<(640 * 512 + 255) / 256, 256>>>(Wl[0], Wr[0], Wl[1], Wr[1], Wl[2], Wr[2]);
    a_convert_kernel<<<(NN * FIN / 4 + 255) / 256, 256>>>(x, pAhi, pAlo, NN * FIN);

    dim3 ggrid(4, (NN + 127) / 128);  // col-strips adjacent -> A read once
    int node_blocks = (NN * 2 * 32 + 255) / 256;

    // Layer 0 (mask self loops)
    gemm_bf16_ldsm_kernel<<<ggrid, 256, 65536>>>(pAhi, pAlo, NN, FIN,
                                                 pWhi, pWlo, bl[0], br[0], pXLR);
    gat_node_kernel<<<node_blocks, 256>>>(pXLR, prow1, pperm1, psrc, wgt,
                                          att[0], We[0], bb[0], 1,
                                          nullptr, pAhi, pAlo);
    // Layer 1
    gemm_bf16_ldsm_kernel<<<ggrid, 256, 65536>>>(pAhi, pAlo, NN, HC,
                                                 pWhi + 128 * 512, pWlo + 128 * 512,
                                                 bl[1], br[1], pXLR);
    gat_node_kernel<<<node_blocks, 256>>>(pXLR, prow1, pperm1, psrc, wgt,
                                          att[1], We[1], bb[1], 0,
                                          nullptr, pAhi, pAlo);
    // Layer 2
    gemm_bf16_ldsm_kernel<<<ggrid, 256, 65536>>>(pAhi, pAlo, NN, HC,
                                                 pWhi + 384 * 512, pWlo + 384 * 512,
                                                 bl[2], br[2], pXLR);
    gat_node_kernel<<<node_blocks, 256>>>(pXLR, prow1, pperm1, psrc, wgt,
                                          att[2], We[2], bb[2], 0,
                                          pHA, nullptr, nullptr);
    // Classifier
    fc_kernel<<<(NN * 32 + 255) / 256, 256>>>(pHA, fcW, fcb, out);
}

// round 9
// speedup vs baseline: 3.0761x; 1.0057x over previous
#include <cuda_runtime.h>
#include <cuda_bf16.h>
#include <math.h>
#include <stdint.h>

#define NN 50000
#define EE 500000
#define ESLN 550000   // EE + NN (edges with self loops)
#define FIN 128
#define HC 256
#define CH 128
#define NCLASS 10
#define NB0 49        // ceil(NN/1024)

// ---------------- scratch (static __device__ globals; no allocation) -------
__device__ int   g_src[ESLN];
__device__ int   g_dst[ESLN];
__device__ int   g_cnt[NN];
__device__ int   g_cursor[NN];
__device__ int   g_rowptr1[NN + 1];
__device__ int   g_perm1[ESLN];
__device__ float g_XLR[(size_t)NN * 512];   // [N,512]: 0..255 = xl, 256..511 = xr
__device__ float g_HA[(size_t)NN * HC];     // final layer f32 output
__device__ __nv_bfloat16 g_Ahi[(size_t)NN * HC];
__device__ __nv_bfloat16 g_Alo[(size_t)NN * HC];
__device__ __nv_bfloat16 g_Whi[640 * 512];  // layer0 rows 0-127, l1 128-383, l2 384-639
__device__ __nv_bfloat16 g_Wlo[640 * 512];
__device__ float g_partial[256];
__device__ float g_wmean;
__device__ int   g_bsum[64];

// ---------------- small utility kernels ------------------------------------
__global__ void zero_int_kernel(int* p, int n) {
    int i = blockIdx.x * blockDim.x + threadIdx.x;
    if (i < n) p[i] = 0;
}

// edge_index may be int32 or int64 depending on JAX x64 config.
__global__ void convert_edges_kernel(const unsigned int* __restrict__ ei,
                                     int* __restrict__ src, int* __restrict__ dst) {
    __shared__ int s_is64;
    if (threadIdx.x == 0) {
        unsigned int acc = 0;
#pragma unroll
        for (int k = 0; k < 32; k++) acc |= ei[2 * k + 1];
        s_is64 = (acc == 0u) ? 1 : 0;
    }
    __syncthreads();
    int is64 = s_is64;
    int i = blockIdx.x * blockDim.x + threadIdx.x;
    if (i >= ESLN) return;
    if (i < EE) {
        int s, d;
        if (is64) {
            const long long* p = reinterpret_cast<const long long*>(ei);
            s = (int)p[i];
            d = (int)p[EE + i];
        } else {
            const int* p = reinterpret_cast<const int*>(ei);
            s = p[i];
            d = p[EE + i];
        }
        src[i] = s;
        dst[i] = d;
    } else {
        int v = i - EE;
        src[i] = v;
        dst[i] = v;
    }
}

__global__ void mean_partial_kernel(const float* __restrict__ w) {
    __shared__ float s[256];
    float acc = 0.f;
    for (int i = blockIdx.x * 256 + threadIdx.x; i < EE; i += 256 * 256) acc += w[i];
    s[threadIdx.x] = acc;
    __syncthreads();
    for (int off = 128; off > 0; off >>= 1) {
        if (threadIdx.x < off) s[threadIdx.x] += s[threadIdx.x + off];
        __syncthreads();
    }
    if (threadIdx.x == 0) g_partial[blockIdx.x] = s[0];
}

__global__ void mean_final_kernel() {
    __shared__ float s[256];
    s[threadIdx.x] = g_partial[threadIdx.x];
    __syncthreads();
    for (int off = 128; off > 0; off >>= 1) {
        if (threadIdx.x < off) s[threadIdx.x] += s[threadIdx.x + off];
        __syncthreads();
    }
    if (threadIdx.x == 0) g_wmean = s[0] / (float)EE;
}

__global__ void hist_kernel(const int* __restrict__ dst, int* __restrict__ cnt, int count) {
    int e = blockIdx.x * blockDim.x + threadIdx.x;
    if (e < count) atomicAdd(&cnt[dst[e]], 1);
}

// ---- 3-phase scan ----
__global__ void scan_local_kernel(const int* __restrict__ cnt, int* __restrict__ rowptr) {
    __shared__ int s[1024];
    int t = threadIdx.x;
    int i = blockIdx.x * 1024 + t;
    int v = (i < NN) ? cnt[i] : 0;
    s[t] = v;
    __syncthreads();
    for (int off = 1; off < 1024; off <<= 1) {
        int x = s[t];
        int y = (t >= off) ? s[t - off] : 0;
        __syncthreads();
        s[t] = x + y;
        __syncthreads();
    }
    if (i < NN) rowptr[i] = s[t] - v;
    if (t == 1023) g_bsum[blockIdx.x] = s[1023];
}

__global__ void scan_bsum_kernel(int* __restrict__ rowptr) {
    __shared__ int s[64];
    int t = threadIdx.x;
    int v = (t < NB0) ? g_bsum[t] : 0;
    s[t] = v;
    __syncthreads();
    for (int off = 1; off < 64; off <<= 1) {
        int x = s[t];
        int y = (t >= off) ? s[t - off] : 0;
        __syncthreads();
        s[t] = x + y;
        __syncthreads();
    }
    if (t < NB0) g_bsum[t] = s[t] - v;
    if (t == 63) rowptr[NN] = s[63];
}

__global__ void scan_add_kernel(int* __restrict__ rowptr, int* __restrict__ cursor) {
    int i = blockIdx.x * 1024 + threadIdx.x;
    if (i < NN) {
        int r = rowptr[i] + g_bsum[blockIdx.x];
        rowptr[i] = r;
        cursor[i] = r;
    }
}

__global__ void scatter_kernel(const int* __restrict__ dst, int* __restrict__ cursor,
                               int* __restrict__ perm, int count) {
    int e = blockIdx.x * blockDim.x + threadIdx.x;
    if (e < count) {
        int p = atomicAdd(&cursor[dst[e]], 1);
        perm[p] = e;
    }
}

// ---------------- bf16 helpers ----------------------------------------------
__device__ __forceinline__ uint32_t pack_bf16(__nv_bfloat16 a, __nv_bfloat16 b) {
    __nv_bfloat162 t = __halves2bfloat162(a, b);
    return *reinterpret_cast<uint32_t*>(&t);
}

__device__ __forceinline__ void split_bf16(float x, __nv_bfloat16& h, __nv_bfloat16& l) {
    h = __float2bfloat16_rn(x);
    l = __float2bfloat16_rn(x - __bfloat162float(h));
}

__device__ __forceinline__ void mma_bf16(float* c, const uint32_t* a, uint32_t b0, uint32_t b1) {
    asm volatile(
        "mma.sync.aligned.m16n8k16.row.col.f32.bf16.bf16.f32 "
        "{%0,%1,%2,%3}, {%4,%5,%6,%7}, {%8,%9}, {%0,%1,%2,%3};"
        : "+f"(c[0]), "+f"(c[1]), "+f"(c[2]), "+f"(c[3])
        : "r"(a[0]), "r"(a[1]), "r"(a[2]), "r"(a[3]), "r"(b0), "r"(b1));
}

__device__ __forceinline__ void ldsm_x4(uint32_t* r, uint32_t saddr) {
    asm volatile("ldmatrix.sync.aligned.m8n8.x4.shared.b16 {%0,%1,%2,%3}, [%4];"
                 : "=r"(r[0]), "=r"(r[1]), "=r"(r[2]), "=r"(r[3]) : "r"(saddr));
}

__device__ __forceinline__ void ldsm_x4_t(uint32_t* r, uint32_t saddr) {
    asm volatile("ldmatrix.sync.aligned.m8n8.x4.trans.shared.b16 {%0,%1,%2,%3}, [%4];"
                 : "=r"(r[0]), "=r"(r[1]), "=r"(r[2]), "=r"(r[3]) : "r"(saddr));
}

__device__ __forceinline__ void cp_async16(uint32_t saddr, const void* g, int sz) {
    asm volatile("cp.async.cg.shared.global [%0], [%1], 16, %2;"
                 :: "r"(saddr), "l"(g), "r"(sz));
}

// ---------------- conversion kernels ----------------------------------------
__global__ void a_convert_kernel(const float* __restrict__ A,
                                 __nv_bfloat16* __restrict__ hi,
                                 __nv_bfloat16* __restrict__ lo, int total) {
    int i = (blockIdx.x * blockDim.x + threadIdx.x) * 4;
    if (i >= total) return;
    float4 v = *reinterpret_cast<const float4*>(A + i);
    __nv_bfloat16 h0, h1, h2, h3, l0, l1, l2, l3;
    split_bf16(v.x, h0, l0); split_bf16(v.y, h1, l1);
    split_bf16(v.z, h2, l2); split_bf16(v.w, h3, l3);
    *reinterpret_cast<uint2*>(hi + i) = make_uint2(pack_bf16(h0, h1), pack_bf16(h2, h3));
    *reinterpret_cast<uint2*>(lo + i) = make_uint2(pack_bf16(l0, l1), pack_bf16(l2, l3));
}

__global__ void w_convert_kernel(const float* __restrict__ Wl0, const float* __restrict__ Wr0,
                                 const float* __restrict__ Wl1, const float* __restrict__ Wr1,
                                 const float* __restrict__ Wl2, const float* __restrict__ Wr2) {
    int i = blockIdx.x * blockDim.x + threadIdx.x;
    if (i >= 640 * 512) return;
    int row = i >> 9, col = i & 511;
    const float *Wl, *Wr;
    int k;
    if (row < 128) { Wl = Wl0; Wr = Wr0; k = row; }
    else if (row < 384) { Wl = Wl1; Wr = Wr1; k = row - 128; }
    else { Wl = Wl2; Wr = Wr2; k = row - 384; }
    float v = (col < 256) ? Wl[k * 256 + col] : Wr[k * 256 + col - 256];
    __nv_bfloat16 h, l;
    split_bf16(v, h, l);
    g_Whi[i] = h;
    g_Wlo[i] = l;
}

// ---------------- GEMM: C[N,512] = A[N,K] @ W + bias -----------------------
// 3xBF16 with pre-split hi/lo operands. cp.async -> swizzled smem -> ldmatrix
// -> mma. Block 128x128, BK=32, 8 warps (2x4), warp tile 64x32.
// Inner loop re-sequenced (volatile asm order) so hi/lo fragments are never
// all live: peak frag regs 32 instead of 48, allowing 2 CTAs/SM
// (__launch_bounds__(256,2)) so cross-CTA overlap hides the k-tile syncs.
__global__ __launch_bounds__(256, 2) void gemm_bf16_ldsm_kernel(
    const __nv_bfloat16* __restrict__ Ahi, const __nv_bfloat16* __restrict__ Alo,
    int Mrows, int K,
    const __nv_bfloat16* __restrict__ Whi, const __nv_bfloat16* __restrict__ Wlo,
    const float* __restrict__ blv, const float* __restrict__ brv,
    float* __restrict__ Cmat) {
    extern __shared__ uint8_t smem[];
    uint32_t sbase = (uint32_t)__cvta_generic_to_shared(smem);
    const int bcol = blockIdx.x * 128;  // within 512
    const int brow = blockIdx.y * 128;
    const int tid = threadIdx.x;
    const int lane = tid & 31;
    const int warp = tid >> 5;
    const int wm = warp >> 2;  // 0..1
    const int wn = warp & 3;   // 0..3

    float acc[4][4][4];
#pragma unroll
    for (int i = 0; i < 4; i++)
#pragma unroll
        for (int j = 0; j < 4; j++)
#pragma unroll
            for (int r = 0; r < 4; r++) acc[i][j][r] = 0.f;

    auto prefetch = [&](int kt, int soff) {
#pragma unroll
        for (int i = 0; i < 2; i++) {
            int c = tid + i * 256;
            int m = c >> 2, kc = c & 3;
            int grow = brow + m;
            int sz = (grow < Mrows) ? 16 : 0;
            uint32_t da = sbase + soff + (m * 4 + (kc ^ ((m >> 1) & 3))) * 16;
            size_t gofs = (size_t)grow * K + kt + kc * 8;
            cp_async16(da, Ahi + gofs, sz);
            cp_async16(da + 8192, Alo + gofs, sz);
        }
#pragma unroll
        for (int i = 0; i < 2; i++) {
            int c = tid + i * 256;
            int k = c >> 4, nc = c & 15;
            uint32_t db = sbase + soff + 16384 + (k * 16 + (nc ^ (k & 7))) * 16;
            size_t gofs = (size_t)(kt + k) * 512 + bcol + nc * 8;
            cp_async16(db, Whi + gofs, 16);
            cp_async16(db + 8192, Wlo + gofs, 16);
        }
        asm volatile("cp.async.commit_group;");
    };

    const int nk = K >> 5;
    prefetch(0, 0);
    asm volatile("cp.async.wait_group 0;");
    __syncthreads();

    const int lr = lane & 7;
    const int sel = lane >> 3;
    int buf = 0;
    for (int it = 0; it < nk; it++) {
        if (it + 1 < nk) prefetch((it + 1) << 5, (buf ^ 1) * 32768);
        int soff = buf * 32768;
#pragma unroll
        for (int s = 0; s < 2; s++) {
            uint32_t afrag[4][4], bfrag[2][4], b2frag[2][4];
            // --- load A-hi and B-hi ---
#pragma unroll
            for (int t = 0; t < 4; t++) {
                int m = wm * 64 + t * 16 + lr + ((sel & 1) << 3);
                int kc = s * 2 + ((sel >> 1) & 1);
                uint32_t addr = sbase + soff + (m * 4 + (kc ^ ((m >> 1) & 3))) * 16;
                ldsm_x4(afrag[t], addr);
            }
#pragma unroll
            for (int j2 = 0; j2 < 2; j2++) {
                int k = s * 16 + ((sel & 1) << 3) + lr;
                int nt = wn * 4 + 2 * j2 + ((sel >> 1) & 1);
                uint32_t addr = sbase + soff + 16384 + (k * 16 + (nt ^ (k & 7))) * 16;
                ldsm_x4_t(bfrag[j2], addr);
            }
            // term1: A_hi * B_hi
#pragma unroll
            for (int i = 0; i < 4; i++)
#pragma unroll
                for (int j = 0; j < 4; j++) {
                    const uint32_t* bp = &bfrag[j >> 1][(j & 1) * 2];
                    mma_bf16(acc[i][j], afrag[i], bp[0], bp[1]);
                }
            // --- load B-lo ---
#pragma unroll
            for (int j2 = 0; j2 < 2; j2++) {
                int k = s * 16 + ((sel & 1) << 3) + lr;
                int nt = wn * 4 + 2 * j2 + ((sel >> 1) & 1);
                uint32_t addr = sbase + soff + 16384 + (k * 16 + (nt ^ (k & 7))) * 16;
                ldsm_x4_t(b2frag[j2], addr + 8192);
            }
            // term2: A_hi * B_lo
#pragma unroll
            for (int i = 0; i < 4; i++)
#pragma unroll
                for (int j = 0; j < 4; j++) {
                    const uint32_t* bp = &b2frag[j >> 1][(j & 1) * 2];
                    mma_bf16(acc[i][j], afrag[i], bp[0], bp[1]);
                }
            // --- load A-lo (A-hi dead, registers reusable) ---
#pragma unroll
            for (int t = 0; t < 4; t++) {
                int m = wm * 64 + t * 16 + lr + ((sel & 1) << 3);
                int kc = s * 2 + ((sel >> 1) & 1);
                uint32_t addr = sbase + soff + (m * 4 + (kc ^ ((m >> 1) & 3))) * 16;
                ldsm_x4(afrag[t], addr + 8192);
            }
            // term3: A_lo * B_hi
#pragma unroll
            for (int i = 0; i < 4; i++)
#pragma unroll
                for (int j = 0; j < 4; j++) {
                    const uint32_t* bp = &bfrag[j >> 1][(j & 1) * 2];
                    mma_bf16(acc[i][j], afrag[i], bp[0], bp[1]);
                }
        }
        if (it + 1 < nk) asm volatile("cp.async.wait_group 0;");
        __syncthreads();
        buf ^= 1;
    }

    // epilogue: bias add + store
    int r0 = lane >> 2;
    int c0 = (lane & 3) * 2;
#pragma unroll
    for (int j = 0; j < 4; j++) {
        int gcol = bcol + wn * 32 + j * 8 + c0;
        float b0v = (gcol < 256) ? blv[gcol] : brv[gcol - 256];
        float b1v = (gcol < 256) ? blv[gcol + 1] : brv[gcol + 1 - 256];
#pragma unroll
        for (int i = 0; i < 4; i++) {
            int grow = brow + wm * 64 + i * 16 + r0;
            if (grow < Mrows) {
                float2 v = make_float2(acc[i][j][0] + b0v, acc[i][j][1] + b1v);
                *reinterpret_cast<float2*>(Cmat + (size_t)grow * 512 + gcol) = v;
            }
            if (grow + 8 < Mrows) {
                float2 v = make_float2(acc[i][j][2] + b0v, acc[i][j][3] + b1v);
                *reinterpret_cast<float2*>(Cmat + (size_t)(grow + 8) * 512 + gcol) = v;
            }
        }
    }
}

// ---------------- fused GATv2 node kernel ------------------------------------
__global__ __launch_bounds__(256) void gat_node_kernel(
    const float* __restrict__ XLR,
    const int* __restrict__ rowptr, const int* __restrict__ perm,
    const int* __restrict__ src, const float* __restrict__ wgt,
    const float* __restrict__ att, const float* __restrict__ We,
    const float* __restrict__ bias, int skipSelf,
    float* __restrict__ HoutF32,
    __nv_bfloat16* __restrict__ OutHi, __nv_bfloat16* __restrict__ OutLo) {
    int wid = (blockIdx.x * blockDim.x + threadIdx.x) >> 5;
    if (wid >= NN * 2) return;
    int lane = threadIdx.x & 31;
    int node = wid >> 1;
    int h = wid & 1;
    int base = h * CH + lane * 4;
    const float4 xr = *reinterpret_cast<const float4*>(XLR + (size_t)node * 512 + 256 + base);
    const float4 av = *reinterpret_cast<const float4*>(att + base);
    const float4 wv = *reinterpret_cast<const float4*>(We + base);
    float d = 0.f;
    float4 acc = make_float4(0.f, 0.f, 0.f, 0.f);
    int i0 = rowptr[node], i1 = rowptr[node + 1];
    float wmean = g_wmean;
    int idx = i0;
#define EDGE_BODY(eV, peV)                                                     \
    {                                                                          \
        int s_ = src[eV];                                                      \
        float ea_ = (eV < EE) ? __ldg(wgt + eV) : wmean;                       \
        float4 xl_ = *reinterpret_cast<const float4*>(XLR + (size_t)s_ * 512 + base); \
        float q0 = xl_.x + xr.x + ea_ * wv.x;                                  \
        float q1 = xl_.y + xr.y + ea_ * wv.y;                                  \
        float q2 = xl_.z + xr.z + ea_ * wv.z;                                  \
        float q3 = xl_.w + xr.w + ea_ * wv.w;                                  \
        q0 = q0 > 0.f ? q0 : 0.2f * q0;                                        \
        q1 = q1 > 0.f ? q1 : 0.2f * q1;                                        \
        q2 = q2 > 0.f ? q2 : 0.2f * q2;                                        \
        q3 = q3 > 0.f ? q3 : 0.2f * q3;                                        \
        peV = q0 * av.x + q1 * av.y + q2 * av.z + q3 * av.w;                   \
        xsave = xl_;                                                           \
    }
    for (; idx + 4 <= i1; idx += 4) {
        int e0 = perm[idx], e1 = perm[idx + 1], e2 = perm[idx + 2], e3 = perm[idx + 3];
        float p0, p1, p2, p3;
        float4 xsave;
        float4 x0, x1, x2, x3;
        EDGE_BODY(e0, p0); x0 = xsave;
        EDGE_BODY(e1, p1); x1 = xsave;
        EDGE_BODY(e2, p2); x2 = xsave;
        EDGE_BODY(e3, p3); x3 = xsave;
#pragma unroll
        for (int off = 16; off >= 1; off >>= 1) {
            p0 += __shfl_xor_sync(0xffffffffu, p0, off);
            p1 += __shfl_xor_sync(0xffffffffu, p1, off);
            p2 += __shfl_xor_sync(0xffffffffu, p2, off);
            p3 += __shfl_xor_sync(0xffffffffu, p3, off);
        }
        float m0 = (skipSelf && e0 >= EE) ? 0.f : 1.f;
        float m1 = (skipSelf && e1 >= EE) ? 0.f : 1.f;
        float m2 = (skipSelf && e2 >= EE) ? 0.f : 1.f;
        float m3 = (skipSelf && e3 >= EE) ? 0.f : 1.f;
        float pe0 = __expf(p0) * m0, pe1 = __expf(p1) * m1;
        float pe2 = __expf(p2) * m2, pe3 = __expf(p3) * m3;
        d += (pe0 + pe1) + (pe2 + pe3);
        acc.x += pe0 * x0.x + pe1 * x1.x + pe2 * x2.x + pe3 * x3.x;
        acc.y += pe0 * x0.y + pe1 * x1.y + pe2 * x2.y + pe3 * x3.y;
        acc.z += pe0 * x0.z + pe1 * x1.z + pe2 * x2.z + pe3 * x3.z;
        acc.w += pe0 * x0.w + pe1 * x1.w + pe2 * x2.w + pe3 * x3.w;
    }
    for (; idx < i1; idx++) {
        int e = perm[idx];
        float p;
        float4 xsave;
        EDGE_BODY(e, p);
#pragma unroll
        for (int off = 16; off >= 1; off >>= 1) p += __shfl_xor_sync(0xffffffffu, p, off);
        float m = (skipSelf && e >= EE) ? 0.f : 1.f;
        float pe = __expf(p) * m;
        d += pe;
        acc.x += pe * xsave.x;
        acc.y += pe * xsave.y;
        acc.z += pe * xsave.z;
        acc.w += pe * xsave.w;
    }
#undef EDGE_BODY
    float inv = (d > 0.f) ? 1.f / (d + 1e-16f) : 0.f;
    const float4 bv = *reinterpret_cast<const float4*>(bias + base);
    float o0 = acc.x * inv + bv.x;
    float o1 = acc.y * inv + bv.y;
    float o2 = acc.z * inv + bv.z;
    float o3 = acc.w * inv + bv.w;
    o0 = o0 > 0.f ? o0 : expm1f(o0);
    o1 = o1 > 0.f ? o1 : expm1f(o1);
    o2 = o2 > 0.f ? o2 : expm1f(o2);
    o3 = o3 > 0.f ? o3 : expm1f(o3);
    if (HoutF32) {
        *reinterpret_cast<float4*>(HoutF32 + (size_t)node * HC + base) =
            make_float4(o0, o1, o2, o3);
    } else {
        __nv_bfloat16 h0, h1, h2, h3, l0, l1, l2, l3;
        split_bf16(o0, h0, l0); split_bf16(o1, h1, l1);
        split_bf16(o2, h2, l2); split_bf16(o3, h3, l3);
        size_t ofs = (size_t)node * HC + base;
        *reinterpret_cast<uint2*>(OutHi + ofs) = make_uint2(pack_bf16(h0, h1), pack_bf16(h2, h3));
        *reinterpret_cast<uint2*>(OutLo + ofs) = make_uint2(pack_bf16(l0, l1), pack_bf16(l2, l3));
    }
}

// ---------------- final classifier ------------------------------------------
__global__ __launch_bounds__(256) void fc_kernel(const float* __restrict__ Hin,
                                                 const float* __restrict__ W,
                                                 const float* __restrict__ b,
                                                 float* __restrict__ out) {
    int wid = (blockIdx.x * blockDim.x + threadIdx.x) >> 5;
    if (wid >= NN) return;
    int lane = threadIdx.x & 31;
    float acc[NCLASS];
#pragma unroll
    for (int k = 0; k < NCLASS; k++) acc[k] = 0.f;
#pragma unroll
    for (int j0 = 0; j0 < HC; j0 += 32) {
        float hv = Hin[(size_t)wid * HC + j0 + lane];
        const float* wr = W + (size_t)(j0 + lane) * NCLASS;
#pragma unroll
        for (int k = 0; k < NCLASS; k++) acc[k] += hv * __ldg(wr + k);
    }
#pragma unroll
    for (int k = 0; k < NCLASS; k++) {
#pragma unroll
        for (int off = 16; off >= 1; off >>= 1)
            acc[k] += __shfl_xor_sync(0xffffffffu, acc[k], off);
    }
    if (lane == 0) {
#pragma unroll
        for (int k = 0; k < NCLASS; k++) out[(size_t)wid * NCLASS + k] = acc[k] + b[k];
    }
}

// ---------------- launch -----------------------------------------------------
extern "C" void kernel_launch(void* const* d_in, const int* in_sizes, int n_in,
                              void* d_out, int out_size) {
    const float* x = (const float*)d_in[0];
    const void* ei = d_in[1];
    const float* wgt = (const float*)d_in[2];
    const float *Wl[3], *bl[3], *Wr[3], *br[3], *We[3], *att[3], *bb[3];
    for (int i = 0; i < 3; i++) {
        int bse = 3 + 7 * i;
        Wl[i] = (const float*)d_in[bse + 0];
        bl[i] = (const float*)d_in[bse + 1];
        Wr[i] = (const float*)d_in[bse + 2];
        br[i] = (const float*)d_in[bse + 3];
        We[i] = (const float*)d_in[bse + 4];
        att[i] = (const float*)d_in[bse + 5];
        bb[i] = (const float*)d_in[bse + 6];
    }
    const float* fcW = (const float*)d_in[24];
    const float* fcb = (const float*)d_in[25];
    float* out = (float*)d_out;

    int *psrc, *pdst, *pcnt, *pcursor, *prow1, *pperm1;
    float *pXLR, *pHA;
    __nv_bfloat16 *pAhi, *pAlo, *pWhi, *pWlo;
    cudaGetSymbolAddress((void**)&psrc, g_src);
    cudaGetSymbolAddress((void**)&pdst, g_dst);
    cudaGetSymbolAddress((void**)&pcnt, g_cnt);
    cudaGetSymbolAddress((void**)&pcursor, g_cursor);
    cudaGetSymbolAddress((void**)&prow1, g_rowptr1);
    cudaGetSymbolAddress((void**)&pperm1, g_perm1);
    cudaGetSymbolAddress((void**)&pXLR, g_XLR);
    cudaGetSymbolAddress((void**)&pHA, g_HA);
    cudaGetSymbolAddress((void**)&pAhi, g_Ahi);
    cudaGetSymbolAddress((void**)&pAlo, g_Alo);
    cudaGetSymbolAddress((void**)&pWhi, g_Whi);
    cudaGetSymbolAddress((void**)&pWlo, g_Wlo);

    cudaFuncSetAttribute(gemm_bf16_ldsm_kernel,
                         cudaFuncAttributeMaxDynamicSharedMemorySize, 65536);

    // edge decode + self loops, weight mean
    convert_edges_kernel<<<(ESLN + 255) / 256, 256>>>((const unsigned int*)ei, psrc, pdst);
    mean_partial_kernel<<<256, 256>>>(wgt);
    mean_final_kernel<<<1, 256>>>();

    // single CSR (with self loops) — layer 0 masks self loops at runtime
    zero_int_kernel<<<(NN + 255) / 256, 256>>>(pcnt, NN);
    hist_kernel<<<(ESLN + 255) / 256, 256>>>(pdst, pcnt, ESLN);
    scan_local_kernel<<<NB0, 1024>>>(pcnt, prow1);
    scan_bsum_kernel<<<1, 64>>>(prow1);
    scan_add_kernel<<<NB0, 1024>>>(prow1, pcursor);
    scatter_kernel<<<(ESLN + 255) / 256, 256>>>(pdst, pcursor, pperm1, ESLN);

    // weights -> bf16 hi/lo; x -> bf16 hi/lo
    w_convert_kernel<<<(640 * 512 + 255) / 256, 256>>>(Wl[0], Wr[0], Wl[1], Wr[1], Wl[2], Wr[2]);
    a_convert_kernel<<<(NN * FIN / 4 + 255) / 256, 256>>>(x, pAhi, pAlo, NN * FIN);

    dim3 ggrid(4, (NN + 127) / 128);  // col-strips adjacent -> A read once
    int node_blocks = (NN * 2 * 32 + 255) / 256;

    // Layer 0 (mask self loops)
    gemm_bf16_ldsm_kernel<<<ggrid, 256, 65536>>>(pAhi, pAlo, NN, FIN,
                                                 pWhi, pWlo, bl[0], br[0], pXLR);
    gat_node_kernel<<<node_blocks, 256>>>(pXLR, prow1, pperm1, psrc, wgt,
                                          att[0], We[0], bb[0], 1,
                                          nullptr, pAhi, pAlo);
    // Layer 1
    gemm_bf16_ldsm_kernel<<<ggrid, 256, 65536>>>(pAhi, pAlo, NN, HC,
                                                 pWhi + 128 * 512, pWlo + 128 * 512,
                                                 bl[1], br[1], pXLR);
    gat_node_kernel<<<node_blocks, 256>>>(pXLR, prow1, pperm1, psrc, wgt,
                                          att[1], We[1], bb[1], 0,
                                          nullptr, pAhi, pAlo);
    // Layer 2
    gemm_bf16_ldsm_kernel<<<ggrid, 256, 65536>>>(pAhi, pAlo, NN, HC,
                                                 pWhi + 384 * 512, pWlo + 384 * 512,
                                                 bl[2], br[2], pXLR);
    gat_node_kernel<<<node_blocks, 256>>>(pXLR, prow1, pperm1, psrc, wgt,
                                          att[2], We[2], bb[2], 0,
                                          pHA, nullptr, nullptr);
    // Classifier
    fc_kernel<<<(NN * 32 + 255) / 256, 256>>>(pHA, fcW, fcb, out);
}